// round 5
// baseline (speedup 1.0000x reference)
#include <cuda_runtime.h>
#include <cuda_bf16.h>

#define N_NODES  50000
#define HID      128
#define EH       64
#define E_TOTAL  800000
#define N_LAYERS 4

typedef unsigned long long u64;

// Persistent scratch (allowed: __device__ globals, no runtime alloc)
__device__ __align__(256) float g_h[N_NODES * HID];     // 25.6 MB, node features
__device__ __align__(256) float g_agg[N_NODES * EH];    // 12.8 MB, message accumulators

__device__ __forceinline__ float silu_f(float x) {
    return x * (1.0f / (1.0f + __expf(-x)));
}

// Vectorized global float4 reduction (sm_90+)
__device__ __forceinline__ void red_add_v4(float* p, float4 v) {
    asm volatile("red.global.add.v4.f32 [%0], {%1,%2,%3,%4};"
                 :: "l"(p), "f"(v.x), "f"(v.y), "f"(v.z), "f"(v.w) : "memory");
}

// ---- packed f32x2 helpers (sm_100+: SASS FFMA2, 2 fp32 FMA per issue) ----
__device__ __forceinline__ u64 splat2(float x) {
    u64 r; unsigned xi = __float_as_uint(x);
    asm("mov.b64 %0, {%1, %1};" : "=l"(r) : "r"(xi));
    return r;
}
__device__ __forceinline__ u64 fma2(u64 a, u64 b, u64 c) {
    u64 d;
    asm("fma.rn.f32x2 %0, %1, %2, %3;" : "=l"(d) : "l"(a), "l"(b), "l"(c));
    return d;
}
__device__ __forceinline__ float lo2(u64 v) { return __uint_as_float((unsigned)v); }
__device__ __forceinline__ float hi2(u64 v) { return __uint_as_float((unsigned)(v >> 32)); }

#define FMA16(A4, B4, ACC) do { \
    ACC[0][0] += A4.x*B4.x; ACC[0][1] += A4.x*B4.y; ACC[0][2] += A4.x*B4.z; ACC[0][3] += A4.x*B4.w; \
    ACC[1][0] += A4.y*B4.x; ACC[1][1] += A4.y*B4.y; ACC[1][2] += A4.y*B4.z; ACC[1][3] += A4.y*B4.w; \
    ACC[2][0] += A4.z*B4.x; ACC[2][1] += A4.z*B4.y; ACC[2][2] += A4.z*B4.z; ACC[2][3] += A4.z*B4.w; \
    ACC[3][0] += A4.w*B4.x; ACC[3][1] += A4.w*B4.y; ACC[3][2] += A4.w*B4.z; ACC[3][3] += A4.w*B4.w; \
} while(0)

// ---------------------------------------------------------------------------
// zero g_agg : exactly 800000 float4 = 50000*64 floats
__global__ void zero_agg_kernel() {
    int i = blockIdx.x * blockDim.x + threadIdx.x;
    ((float4*)g_agg)[i] = make_float4(0.f, 0.f, 0.f, 0.f);
}

// ---------------------------------------------------------------------------
// emb_in: g_h[N,128] = x[N,64] @ W[64,128] + b
__global__ void __launch_bounds__(256) emb_in_kernel(
    const float* __restrict__ x, const float* __restrict__ W, const float* __restrict__ b)
{
    __shared__ float As[64 * 36];   // k-major, stride 36 (pad)
    __shared__ float Bs[64 * 128];
    int tid = threadIdx.x;
    int tx = tid & 31, ty = tid >> 5;
    int n0 = blockIdx.x * 32;

    { // gather A (coalesced rows, transposed store)
        int n = tid >> 3, kk = tid & 7;
        int node = n0 + n;
        #pragma unroll
        for (int it = 0; it < 2; it++) {
            int k4 = kk + it * 8;                     // 0..15 float4 along K=64
            float4 v = make_float4(0.f, 0.f, 0.f, 0.f);
            if (node < N_NODES) v = ((const float4*)(x + node * 64))[k4];
            As[(k4*4+0)*36 + n] = v.x; As[(k4*4+1)*36 + n] = v.y;
            As[(k4*4+2)*36 + n] = v.z; As[(k4*4+3)*36 + n] = v.w;
        }
    }
    { // W [64][128] -> Bs
        const float4* wp = (const float4*)W;
        float4* bp = (float4*)Bs;
        #pragma unroll
        for (int it = 0; it < 8; it++) bp[tid + it * 256] = wp[tid + it * 256];
    }
    __syncthreads();

    float acc[4][4] = {};
    #pragma unroll
    for (int k = 0; k < 64; k++) {
        float4 a  = *(const float4*)(As + k * 36 + ty * 4);
        float4 bb = *(const float4*)(Bs + k * 128 + tx * 4);
        FMA16(a, bb, acc);
    }
    float4 bias = *(const float4*)(b + tx * 4);
    #pragma unroll
    for (int i = 0; i < 4; i++) {
        int node = n0 + ty * 4 + i;
        if (node < N_NODES) {
            float4 v = make_float4(acc[i][0]+bias.x, acc[i][1]+bias.y,
                                   acc[i][2]+bias.z, acc[i][3]+bias.w);
            *((float4*)(g_h + node * 128) + tx) = v;
        }
    }
}

// ---------------------------------------------------------------------------
// edge kernel (FFMA2 version): per block, 64 edges, 128 threads.
//   feat=[h[row],h[col]] (K=256)
//   m1 = silu(feat @ W1 + b1)  [64 x 64]
//   m2 = silu(m1  @ W2 + b2)   [64 x 64]
//   red-add m2 into g_agg[row]
// thread tile: 4 edges x 8 cols (as 4 col-pairs), tx = col grp (8), ty = edge grp (16)
__global__ void __launch_bounds__(128) edge_kernel(
    const int* __restrict__ erow, const int* __restrict__ ecol,
    const float* __restrict__ W1, const float* __restrict__ b1,
    const float* __restrict__ W2, const float* __restrict__ b2)
{
    __shared__ int   sSrc[2][64];
    __shared__ float AstBuf[64 * 68];   // k-major A chunk (pad 68); reused as Ms[64][64]
    __shared__ float Bs[64 * 64];
    int tid = threadIdx.x;
    int tx = tid & 7, ty = tid >> 3;    // tx: 8 col groups (x8), ty: 16 edge groups (x4)
    int e0 = blockIdx.x * 64;

    if (tid < 64)  sSrc[0][tid]      = erow[e0 + tid];
    else           sSrc[1][tid - 64] = ecol[e0 + tid - 64];
    __syncthreads();

    u64 acc[4][4] = {};                 // [edge i][col pair p]; (0,0) bits == (0.0f,0.0f)
    #pragma unroll
    for (int ch = 0; ch < 4; ch++) {    // K chunks: row[0:64],row[64:128],col[0:64],col[64:128]
        if (ch) __syncthreads();
        { // gather A chunk -> k-major smem (128 threads: 8 float4 each)
            int e = tid >> 1, kk = tid & 1;
            int src = sSrc[ch >> 1][e];
            const float4* hp = (const float4*)(g_h + src * 128 + (ch & 1) * 64);
            #pragma unroll
            for (int it = 0; it < 8; it++) {
                int k4 = kk + it * 2;               // 0..15
                float4 v = hp[k4];
                AstBuf[(k4*4+0)*68 + e] = v.x; AstBuf[(k4*4+1)*68 + e] = v.y;
                AstBuf[(k4*4+2)*68 + e] = v.z; AstBuf[(k4*4+3)*68 + e] = v.w;
            }
        }
        { // W1 chunk [64][64] (1024 float4 / 128 thr = 8 each)
            const float4* wp = (const float4*)(W1 + ch * 4096);
            float4* bp = (float4*)Bs;
            #pragma unroll
            for (int it = 0; it < 8; it++) bp[tid + it * 128] = wp[tid + it * 128];
        }
        __syncthreads();
        #pragma unroll
        for (int k = 0; k < 64; k++) {
            float4 a4 = *(const float4*)(AstBuf + k * 68 + ty * 4);
            const u64* bp = (const u64*)(Bs + k * 64 + tx * 8);
            u64 b0 = bp[0], b1v = bp[1], b2v = bp[2], b3v = bp[3];
            u64 s;
            s = splat2(a4.x);
            acc[0][0]=fma2(s,b0,acc[0][0]); acc[0][1]=fma2(s,b1v,acc[0][1]);
            acc[0][2]=fma2(s,b2v,acc[0][2]); acc[0][3]=fma2(s,b3v,acc[0][3]);
            s = splat2(a4.y);
            acc[1][0]=fma2(s,b0,acc[1][0]); acc[1][1]=fma2(s,b1v,acc[1][1]);
            acc[1][2]=fma2(s,b2v,acc[1][2]); acc[1][3]=fma2(s,b3v,acc[1][3]);
            s = splat2(a4.z);
            acc[2][0]=fma2(s,b0,acc[2][0]); acc[2][1]=fma2(s,b1v,acc[2][1]);
            acc[2][2]=fma2(s,b2v,acc[2][2]); acc[2][3]=fma2(s,b3v,acc[2][3]);
            s = splat2(a4.w);
            acc[3][0]=fma2(s,b0,acc[3][0]); acc[3][1]=fma2(s,b1v,acc[3][1]);
            acc[3][2]=fma2(s,b2v,acc[3][2]); acc[3][3]=fma2(s,b3v,acc[3][3]);
        }
    }

    // epilogue 1: bias + silu -> Ms (e-major, k-contiguous), reuse AstBuf
    float4 sb1a = *(const float4*)(b1 + tx * 8);
    float4 sb1b = *(const float4*)(b1 + tx * 8 + 4);
    __syncthreads();                       // all GEMM1 smem reads done
    float* Ms = AstBuf;
    #pragma unroll
    for (int i = 0; i < 4; i++) {
        float4 v0, v1;
        v0.x = silu_f(lo2(acc[i][0]) + sb1a.x);
        v0.y = silu_f(hi2(acc[i][0]) + sb1a.y);
        v0.z = silu_f(lo2(acc[i][1]) + sb1a.z);
        v0.w = silu_f(hi2(acc[i][1]) + sb1a.w);
        v1.x = silu_f(lo2(acc[i][2]) + sb1b.x);
        v1.y = silu_f(hi2(acc[i][2]) + sb1b.y);
        v1.z = silu_f(lo2(acc[i][3]) + sb1b.z);
        v1.w = silu_f(hi2(acc[i][3]) + sb1b.w);
        float* mrow = Ms + (ty * 4 + i) * 64 + tx * 8;
        *(float4*)(mrow)     = v0;
        *(float4*)(mrow + 4) = v1;
    }
    { // W2 [64][64]
        const float4* wp = (const float4*)W2;
        float4* bp = (float4*)Bs;
        #pragma unroll
        for (int it = 0; it < 8; it++) bp[tid + it * 128] = wp[tid + it * 128];
    }
    __syncthreads();

    // GEMM2: acc2[i][p] = sum_k Ms[e_i][k] * W2[k][cols]; Ms rows read as float4 over k
    u64 acc2[4][4] = {};
    #pragma unroll
    for (int k0 = 0; k0 < 64; k0 += 4) {
        float4 am[4];
        #pragma unroll
        for (int i = 0; i < 4; i++)
            am[i] = *(const float4*)(Ms + (ty * 4 + i) * 64 + k0);
        #define G2_STEP(KK, COMP) { \
            const u64* bp = (const u64*)(Bs + (k0 + KK) * 64 + tx * 8); \
            u64 b0 = bp[0], b1v = bp[1], b2v = bp[2], b3v = bp[3]; \
            _Pragma("unroll") \
            for (int i = 0; i < 4; i++) { \
                u64 s = splat2(am[i].COMP); \
                acc2[i][0]=fma2(s,b0,acc2[i][0]); acc2[i][1]=fma2(s,b1v,acc2[i][1]); \
                acc2[i][2]=fma2(s,b2v,acc2[i][2]); acc2[i][3]=fma2(s,b3v,acc2[i][3]); \
            } }
        G2_STEP(0, x)
        G2_STEP(1, y)
        G2_STEP(2, z)
        G2_STEP(3, w)
        #undef G2_STEP
    }

    float4 sb2a = *(const float4*)(b2 + tx * 8);
    float4 sb2b = *(const float4*)(b2 + tx * 8 + 4);
    #pragma unroll
    for (int i = 0; i < 4; i++) {
        int r = sSrc[0][ty * 4 + i];
        float4 v0, v1;
        v0.x = silu_f(lo2(acc2[i][0]) + sb2a.x);
        v0.y = silu_f(hi2(acc2[i][0]) + sb2a.y);
        v0.z = silu_f(lo2(acc2[i][1]) + sb2a.z);
        v0.w = silu_f(hi2(acc2[i][1]) + sb2a.w);
        v1.x = silu_f(lo2(acc2[i][2]) + sb2b.x);
        v1.y = silu_f(hi2(acc2[i][2]) + sb2b.y);
        v1.z = silu_f(lo2(acc2[i][3]) + sb2b.z);
        v1.w = silu_f(hi2(acc2[i][3]) + sb2b.w);
        float* dst = g_agg + r * 64 + tx * 8;
        red_add_v4(dst,     v0);
        red_add_v4(dst + 4, v1);
    }
}

// ---------------------------------------------------------------------------
// node kernel: upd = silu([h, C*agg] @ W1 + b1) @ W2 + b2 ; if mask: h += upd
// mask: int32 (JAX bool materialized as int32 by the harness)
__global__ void __launch_bounds__(256) node_kernel(
    const float* __restrict__ W1, const float* __restrict__ b1,
    const float* __restrict__ W2, const float* __restrict__ b2,
    const int* __restrict__ mask, float C)
{
    extern __shared__ float sm[];
    float* As = sm;                 // 64*36
    float* Bs = sm + 64 * 36;       // 64*128
    float* Ts = Bs + 64 * 128;      // 32*128
    int tid = threadIdx.x;
    int tx = tid & 31, ty = tid >> 5;
    int n0 = blockIdx.x * 32;

    float acc[4][4] = {};
    #pragma unroll
    for (int ch = 0; ch < 3; ch++) {        // K=192: h[0:64], h[64:128], C*agg[0:64]
        __syncthreads();
        {
            int n = tid >> 3, kk = tid & 7;
            int node = n0 + n;
            #pragma unroll
            for (int it = 0; it < 2; it++) {
                int k4 = kk + it * 8;       // 0..15
                float4 v = make_float4(0.f, 0.f, 0.f, 0.f);
                if (node < N_NODES) {
                    if (ch < 2) v = ((const float4*)(g_h + node * 128 + ch * 64))[k4];
                    else {
                        v = ((const float4*)(g_agg + node * 64))[k4];
                        v.x *= C; v.y *= C; v.z *= C; v.w *= C;
                    }
                }
                As[(k4*4+0)*36 + n] = v.x; As[(k4*4+1)*36 + n] = v.y;
                As[(k4*4+2)*36 + n] = v.z; As[(k4*4+3)*36 + n] = v.w;
            }
        }
        { // W1 chunk [64][128]
            const float4* wp = (const float4*)(W1 + ch * 64 * 128);
            float4* bp = (float4*)Bs;
            #pragma unroll
            for (int it = 0; it < 8; it++) bp[tid + it * 256] = wp[tid + it * 256];
        }
        __syncthreads();
        #pragma unroll
        for (int k = 0; k < 64; k++) {
            float4 a  = *(const float4*)(As + k * 36 + ty * 4);
            float4 bb = *(const float4*)(Bs + k * 128 + tx * 4);
            FMA16(a, bb, acc);
        }
    }

    // epilogue 1: bias + silu -> Ts (node-major)
    float4 bias1 = *(const float4*)(b1 + tx * 4);
    #pragma unroll
    for (int i = 0; i < 4; i++) {
        float4 v;
        v.x = silu_f(acc[i][0] + bias1.x);
        v.y = silu_f(acc[i][1] + bias1.y);
        v.z = silu_f(acc[i][2] + bias1.z);
        v.w = silu_f(acc[i][3] + bias1.w);
        *(float4*)(Ts + (ty * 4 + i) * 128 + tx * 4) = v;
    }

    float acc2[4][4] = {};
    #pragma unroll
    for (int ch = 0; ch < 2; ch++) {        // K=128
        __syncthreads();                    // Ts visible / Bs free
        {
            const float4* wp = (const float4*)(W2 + ch * 64 * 128);
            float4* bp = (float4*)Bs;
            #pragma unroll
            for (int it = 0; it < 8; it++) bp[tid + it * 256] = wp[tid + it * 256];
        }
        __syncthreads();
        #pragma unroll
        for (int k = 0; k < 64; k++) {
            float4 bb = *(const float4*)(Bs + k * 128 + tx * 4);
            #pragma unroll
            for (int i = 0; i < 4; i++) {
                float a = Ts[(ty * 4 + i) * 128 + ch * 64 + k];
                acc2[i][0] += a * bb.x; acc2[i][1] += a * bb.y;
                acc2[i][2] += a * bb.z; acc2[i][3] += a * bb.w;
            }
        }
    }

    float4 bias2 = *(const float4*)(b2 + tx * 4);
    #pragma unroll
    for (int i = 0; i < 4; i++) {
        int node = n0 + ty * 4 + i;
        if (node < N_NODES && mask[node] != 0) {
            float4* hp = (float4*)(g_h + node * 128) + tx;
            float4 o = *hp;
            o.x += acc2[i][0] + bias2.x;
            o.y += acc2[i][1] + bias2.y;
            o.z += acc2[i][2] + bias2.z;
            o.w += acc2[i][3] + bias2.w;
            *hp = o;
        }
    }
}

// ---------------------------------------------------------------------------
// emb_out: out[N,64] = g_h[N,128] @ W[128,64] + b
__global__ void __launch_bounds__(256) emb_out_kernel(
    const float* __restrict__ W, const float* __restrict__ b, float* __restrict__ out)
{
    __shared__ float As[64 * 68];
    __shared__ float Bs[64 * 64];
    int tid = threadIdx.x;
    int tx = tid & 15, ty = tid >> 4;
    int n0 = blockIdx.x * 64;

    float acc[4][4] = {};
    #pragma unroll
    for (int ch = 0; ch < 2; ch++) {
        if (ch) __syncthreads();
        {
            int n = tid >> 2, kk = tid & 3;
            int node = n0 + n;
            #pragma unroll
            for (int it = 0; it < 4; it++) {
                int k4 = kk + it * 4;
                float4 v = make_float4(0.f, 0.f, 0.f, 0.f);
                if (node < N_NODES) v = ((const float4*)(g_h + node * 128 + ch * 64))[k4];
                As[(k4*4+0)*68 + n] = v.x; As[(k4*4+1)*68 + n] = v.y;
                As[(k4*4+2)*68 + n] = v.z; As[(k4*4+3)*68 + n] = v.w;
            }
        }
        {
            const float4* wp = (const float4*)(W + ch * 64 * 64);
            float4* bp = (float4*)Bs;
            #pragma unroll
            for (int it = 0; it < 4; it++) bp[tid + it * 256] = wp[tid + it * 256];
        }
        __syncthreads();
        #pragma unroll
        for (int k = 0; k < 64; k++) {
            float4 a  = *(const float4*)(As + k * 68 + ty * 4);
            float4 bb = *(const float4*)(Bs + k * 64 + tx * 4);
            FMA16(a, bb, acc);
        }
    }
    float4 bias = *(const float4*)(b + tx * 4);
    #pragma unroll
    for (int i = 0; i < 4; i++) {
        int node = n0 + ty * 4 + i;
        if (node < N_NODES) {
            float4 v = make_float4(acc[i][0]+bias.x, acc[i][1]+bias.y,
                                   acc[i][2]+bias.z, acc[i][3]+bias.w);
            *((float4*)(out + node * 64) + tx) = v;
        }
    }
}

// ---------------------------------------------------------------------------
extern "C" void kernel_launch(void* const* d_in, const int* in_sizes, int n_in,
                              void* d_out, int out_size)
{
    (void)in_sizes; (void)n_in; (void)out_size;
    const float* h0     = (const float*)d_in[0];
    const int*   ea     = (const int*)d_in[1];      // [2, E]
    const int*   ebp    = (const int*)d_in[2];      // [2, E]
    const int*   ma     = (const int*)d_in[3];      // bool -> int32
    const int*   mb     = (const int*)d_in[4];      // bool -> int32
    const float* w_in   = (const float*)d_in[5];
    const float* b_in   = (const float*)d_in[6];
    const float* w_out  = (const float*)d_in[7];
    const float* b_out  = (const float*)d_in[8];
    const float* ew1    = (const float*)d_in[9];    // [4,256,64]
    const float* eb1    = (const float*)d_in[10];   // [4,64]
    const float* ew2    = (const float*)d_in[11];   // [4,64,64]
    const float* eb2    = (const float*)d_in[12];   // [4,64]
    const float* nw1    = (const float*)d_in[13];   // [4,192,128]
    const float* nb1    = (const float*)d_in[14];   // [4,128]
    const float* nw2    = (const float*)d_in[15];   // [4,128,128]
    const float* nb2    = (const float*)d_in[16];   // [4,128]
    float*       out    = (float*)d_out;

    const int NODE_SMEM = (64 * 36 + 64 * 128 + 32 * 128) * (int)sizeof(float); // 58368
    (void)cudaFuncSetAttribute(node_kernel, cudaFuncAttributeMaxDynamicSharedMemorySize, NODE_SMEM);

    emb_in_kernel<<<(N_NODES + 31) / 32, 256>>>(h0, w_in, b_in);

    for (int l = 0; l < N_LAYERS; l++) {
        const int* er = (l & 1) ? ebp : ea;
        const int* m  = (l & 1) ? mb : ma;
        float C = (l & 1) ? (2.0f / 64.0f) : 1.0f;

        zero_agg_kernel<<<(N_NODES * EH / 4) / 256, 256>>>();
        edge_kernel<<<E_TOTAL / 64, 128>>>(er, er + E_TOTAL,
                                           ew1 + l * 256 * 64, eb1 + l * 64,
                                           ew2 + l * 64 * 64,  eb2 + l * 64);
        node_kernel<<<(N_NODES + 31) / 32, 256, NODE_SMEM>>>(
            nw1 + l * 192 * 128, nb1 + l * 128,
            nw2 + l * 128 * 128, nb2 + l * 128, m, C);
    }

    emb_out_kernel<<<(N_NODES + 63) / 64, 256>>>(w_out, b_out, out);
}

// round 6
// speedup vs baseline: 2.1351x; 2.1351x over previous
#include <cuda_runtime.h>
#include <cuda_bf16.h>

#define N_NODES  50000
#define HID      128
#define EH       64
#define E_TOTAL  800000
#define N_LAYERS 4

typedef unsigned int uint;

// Persistent scratch (allowed: __device__ globals, no runtime alloc)
__device__ __align__(256) float g_h[N_NODES * HID];     // 25.6 MB node features
__device__ __align__(256) float g_agg[N_NODES * EH];    // 12.8 MB message accumulators
// Fragment-ordered TF32 weights for the edge MLP (built by prep kernel each launch)
__device__ __align__(256) float g_w1frag[4 * 4 * 8 * 8 * 32 * 2];  // [l][chunk][kstep][ntile][lane][2]
__device__ __align__(256) float g_w2frag[4 * 8 * 8 * 32 * 2];      // [l][kstep][ntile][lane][2]

__device__ __forceinline__ float silu_f(float x) {
    return x * (1.0f / (1.0f + __expf(-x)));
}
__device__ __forceinline__ void red_add_v2(float* p, float x, float y) {
    asm volatile("red.global.add.v2.f32 [%0], {%1,%2};" :: "l"(p), "f"(x), "f"(y) : "memory");
}
__device__ __forceinline__ uint cvt_tf32(float x) {
    uint r; asm("cvt.rna.tf32.f32 %0, %1;" : "=r"(r) : "f"(x)); return r;
}
__device__ __forceinline__ void mma_tf32(float c[4], uint4 a, uint2 b) {
    asm("mma.sync.aligned.m16n8k8.row.col.f32.tf32.tf32.f32 "
        "{%0,%1,%2,%3},{%4,%5,%6,%7},{%8,%9},{%0,%1,%2,%3};"
        : "+f"(c[0]), "+f"(c[1]), "+f"(c[2]), "+f"(c[3])
        : "r"(a.x), "r"(a.y), "r"(a.z), "r"(a.w), "r"(b.x), "r"(b.y));
}

#define FMA16(A4, B4, ACC) do { \
    ACC[0][0] += A4.x*B4.x; ACC[0][1] += A4.x*B4.y; ACC[0][2] += A4.x*B4.z; ACC[0][3] += A4.x*B4.w; \
    ACC[1][0] += A4.y*B4.x; ACC[1][1] += A4.y*B4.y; ACC[1][2] += A4.y*B4.z; ACC[1][3] += A4.y*B4.w; \
    ACC[2][0] += A4.z*B4.x; ACC[2][1] += A4.z*B4.y; ACC[2][2] += A4.z*B4.z; ACC[2][3] += A4.z*B4.w; \
    ACC[3][0] += A4.w*B4.x; ACC[3][1] += A4.w*B4.y; ACC[3][2] += A4.w*B4.z; ACC[3][3] += A4.w*B4.w; \
} while(0)

// ---------------------------------------------------------------------------
__global__ void zero_agg_kernel() {
    int i = blockIdx.x * blockDim.x + threadIdx.x;
    ((float4*)g_agg)[i] = make_float4(0.f, 0.f, 0.f, 0.f);
}

// ---------------------------------------------------------------------------
// Build fragment-ordered TF32 copies of edge weights.
// W1frag element (l,chunk,kstep,ntile,lane,reg): k = chunk*64+kstep*8+(lane&3)+reg*4,
// n = ntile*8+(lane>>2). W2frag: same without chunk, K=64.
__global__ void __launch_bounds__(256) prep_wfrag_kernel(
    const float* __restrict__ ew1, const float* __restrict__ ew2)
{
    int i = blockIdx.x * 256 + threadIdx.x;     // 81920 total
    if (i < 65536) {
        int reg = i & 1, lane = (i >> 1) & 31, nt = (i >> 6) & 7,
            ks = (i >> 9) & 7, ch = (i >> 12) & 3, l = i >> 14;
        int k = ch * 64 + ks * 8 + (lane & 3) + reg * 4;
        int n = nt * 8 + (lane >> 2);
        g_w1frag[i] = __uint_as_float(cvt_tf32(ew1[(l * 256 + k) * 64 + n]));
    } else {
        int j = i - 65536;
        int reg = j & 1, lane = (j >> 1) & 31, nt = (j >> 6) & 7,
            ks = (j >> 9) & 7, l = j >> 12;
        int k = ks * 8 + (lane & 3) + reg * 4;
        int n = nt * 8 + (lane >> 2);
        g_w2frag[j] = __uint_as_float(cvt_tf32(ew2[(l * 64 + k) * 64 + n]));
    }
}

// ---------------------------------------------------------------------------
// emb_in: g_h[N,128] = x[N,64] @ W[64,128] + b  (fp32 scalar)
__global__ void __launch_bounds__(256) emb_in_kernel(
    const float* __restrict__ x, const float* __restrict__ W, const float* __restrict__ b)
{
    __shared__ float As[64 * 36];
    __shared__ float Bs[64 * 128];
    int tid = threadIdx.x;
    int tx = tid & 31, ty = tid >> 5;
    int n0 = blockIdx.x * 32;

    {
        int n = tid >> 3, kk = tid & 7;
        int node = n0 + n;
        #pragma unroll
        for (int it = 0; it < 2; it++) {
            int k4 = kk + it * 8;
            float4 v = make_float4(0.f, 0.f, 0.f, 0.f);
            if (node < N_NODES) v = ((const float4*)(x + node * 64))[k4];
            As[(k4*4+0)*36 + n] = v.x; As[(k4*4+1)*36 + n] = v.y;
            As[(k4*4+2)*36 + n] = v.z; As[(k4*4+3)*36 + n] = v.w;
        }
    }
    {
        const float4* wp = (const float4*)W;
        float4* bp = (float4*)Bs;
        #pragma unroll
        for (int it = 0; it < 8; it++) bp[tid + it * 256] = wp[tid + it * 256];
    }
    __syncthreads();

    float acc[4][4] = {};
    #pragma unroll
    for (int k = 0; k < 64; k++) {
        float4 a  = *(const float4*)(As + k * 36 + ty * 4);
        float4 bb = *(const float4*)(Bs + k * 128 + tx * 4);
        FMA16(a, bb, acc);
    }
    float4 bias = *(const float4*)(b + tx * 4);
    #pragma unroll
    for (int i = 0; i < 4; i++) {
        int node = n0 + ty * 4 + i;
        if (node < N_NODES) {
            float4 v = make_float4(acc[i][0]+bias.x, acc[i][1]+bias.y,
                                   acc[i][2]+bias.z, acc[i][3]+bias.w);
            *((float4*)(g_h + node * 128) + tx) = v;
        }
    }
}

// ---------------------------------------------------------------------------
// edge kernel (TF32 tensor-core): 64 edges/block, 128 threads (4 warps).
// Warp w owns rows [16w,16w+16). mma.m16n8k8, 8 n-tiles, K1=256 (4 chunks), K2=64.
__global__ void __launch_bounds__(128) edge_kernel_tc(
    const int* __restrict__ erow, const int* __restrict__ ecol,
    const float* __restrict__ w1f, const float* __restrict__ b1,
    const float* __restrict__ w2f, const float* __restrict__ b2)
{
    __shared__ int   sSrc[2][64];
    __shared__ float Af[4096];   // A fragments: [kstep(8)][mtile(4)][lane(32)][slot(4)]
    __shared__ float Bf[4096];   // B fragments: [kstep(8)][ntile(8)][lane(32)][reg(2)]
    int tid = threadIdx.x;
    int lane = tid & 31, w = tid >> 5;
    int g = lane >> 2, tig = lane & 3;
    int e0 = blockIdx.x * 64;

    if (tid < 64) sSrc[0][tid]      = erow[e0 + tid];
    else          sSrc[1][tid - 64] = ecol[e0 + tid - 64];
    __syncthreads();

    float c[8][4] = {};
    #pragma unroll
    for (int ch = 0; ch < 4; ch++) {     // K chunks: row[0:64],row[64:128],col[0:64],col[64:128]
        if (ch) __syncthreads();
        { // gather A chunk in fragment order (with TF32 rounding)
            int e = tid >> 1, kk = tid & 1;
            int src = sSrc[ch >> 1][e];
            const float4* hp = (const float4*)(g_h + src * 128 + (ch & 1) * 64);
            int mt = e >> 4, gl = e & 7, hf = (e >> 3) & 1;
            #pragma unroll
            for (int it = 0; it < 8; it++) {
                int k4 = kk + it * 2;
                float4 v = hp[k4];
                #pragma unroll
                for (int j = 0; j < 4; j++) {
                    int kl = k4 * 4 + j;
                    int ks = kl >> 3, tg = kl & 3, kh = (kl >> 2) & 1;
                    float val = (j == 0) ? v.x : (j == 1) ? v.y : (j == 2) ? v.z : v.w;
                    Af[((ks * 4 + mt) * 32 + gl * 4 + tg) * 4 + hf + 2 * kh] =
                        __uint_as_float(cvt_tf32(val));
                }
            }
        }
        { // W1 fragment chunk (16KB)
            const float4* wp = (const float4*)(w1f + ch * 4096);
            float4* bp = (float4*)Bf;
            #pragma unroll
            for (int it = 0; it < 8; it++) bp[tid + it * 128] = wp[tid + it * 128];
        }
        __syncthreads();
        #pragma unroll
        for (int ks = 0; ks < 8; ks++) {
            uint4 a = *(const uint4*)(Af + ((ks * 4 + w) * 32 + lane) * 4);
            #pragma unroll
            for (int nt = 0; nt < 8; nt++) {
                uint2 b = *(const uint2*)(Bf + ((ks * 8 + nt) * 32 + lane) * 2);
                mma_tf32(c[nt], a, b);
            }
        }
    }
    __syncthreads();   // GEMM1 smem reads done

    // m1 epilogue: bias+silu, write into Af in GEMM2 A-fragment layout (kstep2 = nt)
    #pragma unroll
    for (int nt = 0; nt < 8; nt++) {
        int n0 = nt * 8 + 2 * tig;
        float bn0 = b1[n0], bn1 = b1[n0 + 1];
        float v0 = silu_f(c[nt][0] + bn0), v1 = silu_f(c[nt][1] + bn1);
        float v2 = silu_f(c[nt][2] + bn0), v3 = silu_f(c[nt][3] + bn1);
        int t0 = n0 & 3,        h0 = (n0 >> 2) & 1;
        int t1 = (n0 + 1) & 3,  h1 = ((n0 + 1) >> 2) & 1;
        Af[((nt * 4 + w) * 32 + g * 4 + t0) * 4 + 0 + 2 * h0] = __uint_as_float(cvt_tf32(v0));
        Af[((nt * 4 + w) * 32 + g * 4 + t1) * 4 + 0 + 2 * h1] = __uint_as_float(cvt_tf32(v1));
        Af[((nt * 4 + w) * 32 + g * 4 + t0) * 4 + 1 + 2 * h0] = __uint_as_float(cvt_tf32(v2));
        Af[((nt * 4 + w) * 32 + g * 4 + t1) * 4 + 1 + 2 * h1] = __uint_as_float(cvt_tf32(v3));
    }
    { // W2 fragments (16KB)
        const float4* wp = (const float4*)w2f;
        float4* bp = (float4*)Bf;
        #pragma unroll
        for (int it = 0; it < 8; it++) bp[tid + it * 128] = wp[tid + it * 128];
    }
    #pragma unroll
    for (int nt = 0; nt < 8; nt++)
        #pragma unroll
        for (int i = 0; i < 4; i++) c[nt][i] = 0.f;
    __syncthreads();

    // GEMM2: m2 = m1 @ W2, K=64
    #pragma unroll
    for (int ks = 0; ks < 8; ks++) {
        uint4 a = *(const uint4*)(Af + ((ks * 4 + w) * 32 + lane) * 4);
        #pragma unroll
        for (int nt = 0; nt < 8; nt++) {
            uint2 b = *(const uint2*)(Bf + ((ks * 8 + nt) * 32 + lane) * 2);
            mma_tf32(c[nt], a, b);
        }
    }

    // final epilogue: bias+silu, scatter-add to g_agg[row]
    int r0 = w * 16 + g;
    int dst0 = sSrc[0][r0], dst1 = sSrc[0][r0 + 8];
    #pragma unroll
    for (int nt = 0; nt < 8; nt++) {
        int n0 = nt * 8 + 2 * tig;
        float bn0 = b2[n0], bn1 = b2[n0 + 1];
        float v0 = silu_f(c[nt][0] + bn0), v1 = silu_f(c[nt][1] + bn1);
        float v2 = silu_f(c[nt][2] + bn0), v3 = silu_f(c[nt][3] + bn1);
        red_add_v2(g_agg + dst0 * 64 + n0, v0, v1);
        red_add_v2(g_agg + dst1 * 64 + n0, v2, v3);
    }
}

// ---------------------------------------------------------------------------
// node kernel (fp32): upd = silu([h, C*agg] @ W1 + b1) @ W2 + b2 ; if mask: h += upd
__global__ void __launch_bounds__(256) node_kernel(
    const float* __restrict__ W1, const float* __restrict__ b1,
    const float* __restrict__ W2, const float* __restrict__ b2,
    const int* __restrict__ mask, float C)
{
    extern __shared__ float sm[];
    float* As = sm;                 // 64*36
    float* Bs = sm + 64 * 36;       // 64*128
    float* Ts = Bs + 64 * 128;      // 32*128
    int tid = threadIdx.x;
    int tx = tid & 31, ty = tid >> 5;
    int n0 = blockIdx.x * 32;

    float acc[4][4] = {};
    #pragma unroll
    for (int ch = 0; ch < 3; ch++) {        // K=192: h[0:64], h[64:128], C*agg[0:64]
        __syncthreads();
        {
            int n = tid >> 3, kk = tid & 7;
            int node = n0 + n;
            #pragma unroll
            for (int it = 0; it < 2; it++) {
                int k4 = kk + it * 8;
                float4 v = make_float4(0.f, 0.f, 0.f, 0.f);
                if (node < N_NODES) {
                    if (ch < 2) v = ((const float4*)(g_h + node * 128 + ch * 64))[k4];
                    else {
                        v = ((const float4*)(g_agg + node * 64))[k4];
                        v.x *= C; v.y *= C; v.z *= C; v.w *= C;
                    }
                }
                As[(k4*4+0)*36 + n] = v.x; As[(k4*4+1)*36 + n] = v.y;
                As[(k4*4+2)*36 + n] = v.z; As[(k4*4+3)*36 + n] = v.w;
            }
        }
        {
            const float4* wp = (const float4*)(W1 + ch * 64 * 128);
            float4* bp = (float4*)Bs;
            #pragma unroll
            for (int it = 0; it < 8; it++) bp[tid + it * 256] = wp[tid + it * 256];
        }
        __syncthreads();
        #pragma unroll
        for (int k = 0; k < 64; k++) {
            float4 a  = *(const float4*)(As + k * 36 + ty * 4);
            float4 bb = *(const float4*)(Bs + k * 128 + tx * 4);
            FMA16(a, bb, acc);
        }
    }

    float4 bias1 = *(const float4*)(b1 + tx * 4);
    #pragma unroll
    for (int i = 0; i < 4; i++) {
        float4 v;
        v.x = silu_f(acc[i][0] + bias1.x);
        v.y = silu_f(acc[i][1] + bias1.y);
        v.z = silu_f(acc[i][2] + bias1.z);
        v.w = silu_f(acc[i][3] + bias1.w);
        *(float4*)(Ts + (ty * 4 + i) * 128 + tx * 4) = v;
    }

    float acc2[4][4] = {};
    #pragma unroll
    for (int ch = 0; ch < 2; ch++) {        // K=128
        __syncthreads();
        {
            const float4* wp = (const float4*)(W2 + ch * 64 * 128);
            float4* bp = (float4*)Bs;
            #pragma unroll
            for (int it = 0; it < 8; it++) bp[tid + it * 256] = wp[tid + it * 256];
        }
        __syncthreads();
        #pragma unroll
        for (int k = 0; k < 64; k++) {
            float4 bb = *(const float4*)(Bs + k * 128 + tx * 4);
            #pragma unroll
            for (int i = 0; i < 4; i++) {
                float a = Ts[(ty * 4 + i) * 128 + ch * 64 + k];
                acc2[i][0] += a * bb.x; acc2[i][1] += a * bb.y;
                acc2[i][2] += a * bb.z; acc2[i][3] += a * bb.w;
            }
        }
    }

    float4 bias2 = *(const float4*)(b2 + tx * 4);
    #pragma unroll
    for (int i = 0; i < 4; i++) {
        int node = n0 + ty * 4 + i;
        if (node < N_NODES && mask[node] != 0) {
            float4* hp = (float4*)(g_h + node * 128) + tx;
            float4 o = *hp;
            o.x += acc2[i][0] + bias2.x;
            o.y += acc2[i][1] + bias2.y;
            o.z += acc2[i][2] + bias2.z;
            o.w += acc2[i][3] + bias2.w;
            *hp = o;
        }
    }
}

// ---------------------------------------------------------------------------
// emb_out: out[N,64] = g_h[N,128] @ W[128,64] + b  (fp32 scalar)
__global__ void __launch_bounds__(256) emb_out_kernel(
    const float* __restrict__ W, const float* __restrict__ b, float* __restrict__ out)
{
    __shared__ float As[64 * 68];
    __shared__ float Bs[64 * 64];
    int tid = threadIdx.x;
    int tx = tid & 15, ty = tid >> 4;
    int n0 = blockIdx.x * 64;

    float acc[4][4] = {};
    #pragma unroll
    for (int ch = 0; ch < 2; ch++) {
        if (ch) __syncthreads();
        {
            int n = tid >> 2, kk = tid & 3;
            int node = n0 + n;
            #pragma unroll
            for (int it = 0; it < 4; it++) {
                int k4 = kk + it * 4;
                float4 v = make_float4(0.f, 0.f, 0.f, 0.f);
                if (node < N_NODES) v = ((const float4*)(g_h + node * 128 + ch * 64))[k4];
                As[(k4*4+0)*68 + n] = v.x; As[(k4*4+1)*68 + n] = v.y;
                As[(k4*4+2)*68 + n] = v.z; As[(k4*4+3)*68 + n] = v.w;
            }
        }
        {
            const float4* wp = (const float4*)(W + ch * 64 * 64);
            float4* bp = (float4*)Bs;
            #pragma unroll
            for (int it = 0; it < 4; it++) bp[tid + it * 256] = wp[tid + it * 256];
        }
        __syncthreads();
        #pragma unroll
        for (int k = 0; k < 64; k++) {
            float4 a  = *(const float4*)(As + k * 68 + ty * 4);
            float4 bb = *(const float4*)(Bs + k * 64 + tx * 4);
            FMA16(a, bb, acc);
        }
    }
    float4 bias = *(const float4*)(b + tx * 4);
    #pragma unroll
    for (int i = 0; i < 4; i++) {
        int node = n0 + ty * 4 + i;
        if (node < N_NODES) {
            float4 v = make_float4(acc[i][0]+bias.x, acc[i][1]+bias.y,
                                   acc[i][2]+bias.z, acc[i][3]+bias.w);
            *((float4*)(out + node * 64) + tx) = v;
        }
    }
}

// ---------------------------------------------------------------------------
extern "C" void kernel_launch(void* const* d_in, const int* in_sizes, int n_in,
                              void* d_out, int out_size)
{
    (void)in_sizes; (void)n_in; (void)out_size;
    const float* h0     = (const float*)d_in[0];
    const int*   ea     = (const int*)d_in[1];      // [2, E]
    const int*   ebp    = (const int*)d_in[2];      // [2, E]
    const int*   ma     = (const int*)d_in[3];      // bool -> int32
    const int*   mb     = (const int*)d_in[4];      // bool -> int32
    const float* w_in   = (const float*)d_in[5];
    const float* b_in   = (const float*)d_in[6];
    const float* w_out  = (const float*)d_in[7];
    const float* b_out  = (const float*)d_in[8];
    const float* ew1    = (const float*)d_in[9];    // [4,256,64]
    const float* eb1    = (const float*)d_in[10];   // [4,64]
    const float* ew2    = (const float*)d_in[11];   // [4,64,64]
    const float* eb2    = (const float*)d_in[12];   // [4,64]
    const float* nw1    = (const float*)d_in[13];   // [4,192,128]
    const float* nb1    = (const float*)d_in[14];   // [4,128]
    const float* nw2    = (const float*)d_in[15];   // [4,128,128]
    const float* nb2    = (const float*)d_in[16];   // [4,128]
    float*       out    = (float*)d_out;

    const int NODE_SMEM = (64 * 36 + 64 * 128 + 32 * 128) * (int)sizeof(float); // 58368
    (void)cudaFuncSetAttribute(node_kernel, cudaFuncAttributeMaxDynamicSharedMemorySize, NODE_SMEM);

    float* w1frag_base; cudaGetSymbolAddress((void**)&w1frag_base, g_w1frag);
    float* w2frag_base; cudaGetSymbolAddress((void**)&w2frag_base, g_w2frag);

    prep_wfrag_kernel<<<320, 256>>>(ew1, ew2);          // 81920 elements
    emb_in_kernel<<<(N_NODES + 31) / 32, 256>>>(h0, w_in, b_in);

    for (int l = 0; l < N_LAYERS; l++) {
        const int* er = (l & 1) ? ebp : ea;
        const int* m  = (l & 1) ? mb : ma;
        float C = (l & 1) ? (2.0f / 64.0f) : 1.0f;

        zero_agg_kernel<<<(N_NODES * EH / 4) / 256, 256>>>();
        edge_kernel_tc<<<E_TOTAL / 64, 128>>>(
            er, er + E_TOTAL,
            w1frag_base + l * 16384, eb1 + l * 64,
            w2frag_base + l * 4096,  eb2 + l * 64);
        node_kernel<<<(N_NODES + 31) / 32, 256, NODE_SMEM>>>(
            nw1 + l * 192 * 128, nb1 + l * 128,
            nw2 + l * 128 * 128, nb2 + l * 128, m, C);
    }

    emb_out_kernel<<<(N_NODES + 63) / 64, 256>>>(w_out, b_out, out);
}

// round 7
// speedup vs baseline: 2.2219x; 1.0406x over previous
#include <cuda_runtime.h>
#include <cuda_bf16.h>

#define N_NODES  50000
#define HID      128
#define EH       64
#define E_TOTAL  800000
#define N_LAYERS 4

typedef unsigned int uint;

// Persistent scratch (allowed: __device__ globals, no runtime alloc)
__device__ __align__(256) float g_h[N_NODES * HID];     // 25.6 MB node features
__device__ __align__(256) float g_agg[N_NODES * EH];    // 12.8 MB message accumulators
// Fragment-ordered TF32 weights for the edge MLP (built by prep kernel each launch)
__device__ __align__(256) float g_w1frag[4 * 4 * 8 * 8 * 32 * 2];  // [l][chunk][kstep][ntile][lane][2]
__device__ __align__(256) float g_w2frag[4 * 8 * 8 * 32 * 2];      // [l][kstep][ntile][lane][2]

__device__ __forceinline__ float silu_f(float x) {
    return x * (1.0f / (1.0f + __expf(-x)));
}
__device__ __forceinline__ void red_add_v2(float* p, float x, float y) {
    asm volatile("red.global.add.v2.f32 [%0], {%1,%2};" :: "l"(p), "f"(x), "f"(y) : "memory");
}
__device__ __forceinline__ uint cvt_tf32(float x) {
    uint r; asm("cvt.rna.tf32.f32 %0, %1;" : "=r"(r) : "f"(x)); return r;
}
__device__ __forceinline__ void mma_tf32(float c[4], uint4 a, uint2 b) {
    asm("mma.sync.aligned.m16n8k8.row.col.f32.tf32.tf32.f32 "
        "{%0,%1,%2,%3},{%4,%5,%6,%7},{%8,%9},{%0,%1,%2,%3};"
        : "+f"(c[0]), "+f"(c[1]), "+f"(c[2]), "+f"(c[3])
        : "r"(a.x), "r"(a.y), "r"(a.z), "r"(a.w), "r"(b.x), "r"(b.y));
}
// Build mma A-fragment from row-major smem rows (conflict-free with stride 68)
__device__ __forceinline__ uint4 ld_a_frag(const float* a0, const float* a1, int tig) {
    uint4 a;
    a.x = cvt_tf32(a0[tig]);
    a.y = cvt_tf32(a1[tig]);
    a.z = cvt_tf32(a0[tig + 4]);
    a.w = cvt_tf32(a1[tig + 4]);
    return a;
}

#define FMA16(A4, B4, ACC) do { \
    ACC[0][0] += A4.x*B4.x; ACC[0][1] += A4.x*B4.y; ACC[0][2] += A4.x*B4.z; ACC[0][3] += A4.x*B4.w; \
    ACC[1][0] += A4.y*B4.x; ACC[1][1] += A4.y*B4.y; ACC[1][2] += A4.y*B4.z; ACC[1][3] += A4.y*B4.w; \
    ACC[2][0] += A4.z*B4.x; ACC[2][1] += A4.z*B4.y; ACC[2][2] += A4.z*B4.z; ACC[2][3] += A4.z*B4.w; \
    ACC[3][0] += A4.w*B4.x; ACC[3][1] += A4.w*B4.y; ACC[3][2] += A4.w*B4.z; ACC[3][3] += A4.w*B4.w; \
} while(0)

// ---------------------------------------------------------------------------
__global__ void zero_agg_kernel() {
    int i = blockIdx.x * blockDim.x + threadIdx.x;
    ((float4*)g_agg)[i] = make_float4(0.f, 0.f, 0.f, 0.f);
}

// ---------------------------------------------------------------------------
// Build fragment-ordered TF32 copies of edge weights.
// W1frag element (l,chunk,kstep,ntile,lane,reg): k = chunk*64+kstep*8+(lane&3)+reg*4,
// n = ntile*8+(lane>>2). W2frag: same without chunk, K=64.
__global__ void __launch_bounds__(256) prep_wfrag_kernel(
    const float* __restrict__ ew1, const float* __restrict__ ew2)
{
    int i = blockIdx.x * 256 + threadIdx.x;     // 81920 total
    if (i < 65536) {
        int reg = i & 1, lane = (i >> 1) & 31, nt = (i >> 6) & 7,
            ks = (i >> 9) & 7, ch = (i >> 12) & 3, l = i >> 14;
        int k = ch * 64 + ks * 8 + (lane & 3) + reg * 4;
        int n = nt * 8 + (lane >> 2);
        g_w1frag[i] = __uint_as_float(cvt_tf32(ew1[(l * 256 + k) * 64 + n]));
    } else {
        int j = i - 65536;
        int reg = j & 1, lane = (j >> 1) & 31, nt = (j >> 6) & 7,
            ks = (j >> 9) & 7, l = j >> 12;
        int k = ks * 8 + (lane & 3) + reg * 4;
        int n = nt * 8 + (lane >> 2);
        g_w2frag[j] = __uint_as_float(cvt_tf32(ew2[(l * 64 + k) * 64 + n]));
    }
}

// ---------------------------------------------------------------------------
// emb_in: g_h[N,128] = x[N,64] @ W[64,128] + b  (fp32 scalar)
__global__ void __launch_bounds__(256) emb_in_kernel(
    const float* __restrict__ x, const float* __restrict__ W, const float* __restrict__ b)
{
    __shared__ float As[64 * 36];
    __shared__ float Bs[64 * 128];
    int tid = threadIdx.x;
    int tx = tid & 31, ty = tid >> 5;
    int n0 = blockIdx.x * 32;

    {
        int n = tid >> 3, kk = tid & 7;
        int node = n0 + n;
        #pragma unroll
        for (int it = 0; it < 2; it++) {
            int k4 = kk + it * 8;
            float4 v = make_float4(0.f, 0.f, 0.f, 0.f);
            if (node < N_NODES) v = ((const float4*)(x + node * 64))[k4];
            As[(k4*4+0)*36 + n] = v.x; As[(k4*4+1)*36 + n] = v.y;
            As[(k4*4+2)*36 + n] = v.z; As[(k4*4+3)*36 + n] = v.w;
        }
    }
    {
        const float4* wp = (const float4*)W;
        float4* bp = (float4*)Bs;
        #pragma unroll
        for (int it = 0; it < 8; it++) bp[tid + it * 256] = wp[tid + it * 256];
    }
    __syncthreads();

    float acc[4][4] = {};
    #pragma unroll
    for (int k = 0; k < 64; k++) {
        float4 a  = *(const float4*)(As + k * 36 + ty * 4);
        float4 bb = *(const float4*)(Bs + k * 128 + tx * 4);
        FMA16(a, bb, acc);
    }
    float4 bias = *(const float4*)(b + tx * 4);
    #pragma unroll
    for (int i = 0; i < 4; i++) {
        int node = n0 + ty * 4 + i;
        if (node < N_NODES) {
            float4 v = make_float4(acc[i][0]+bias.x, acc[i][1]+bias.y,
                                   acc[i][2]+bias.z, acc[i][3]+bias.w);
            *((float4*)(g_h + node * 128) + tx) = v;
        }
    }
}

// ---------------------------------------------------------------------------
// edge kernel (TF32 tensor-core): 64 edges/block, 128 threads (4 warps).
// A staged ROW-MAJOR in smem (stride 68): vectorized STS.128 gather,
// conflict-free scalar LDS fragment builds (banks g*4+tig cover all 32).
// Warp w owns rows [16w,16w+16). mma.m16n8k8, 8 n-tiles, K1=256 (4 chunks), K2=64.
__global__ void __launch_bounds__(128) edge_kernel_tc(
    const int* __restrict__ erow, const int* __restrict__ ecol,
    const float* __restrict__ w1f, const float* __restrict__ b1,
    const float* __restrict__ w2f, const float* __restrict__ b2)
{
    __shared__ int   sSrc[2][64];
    __shared__ float As[64 * 68];   // row-major A chunk (pad 68); reused as Ms[64][64]
    __shared__ float Bf[4096];      // W fragments: [kstep(8)][ntile(8)][lane(32)][reg(2)]
    int tid = threadIdx.x;
    int lane = tid & 31, w = tid >> 5;
    int g = lane >> 2, tig = lane & 3;
    int e0 = blockIdx.x * 64;

    if (tid < 64) sSrc[0][tid]      = erow[e0 + tid];
    else          sSrc[1][tid - 64] = ecol[e0 + tid - 64];
    __syncthreads();

    int row0 = w * 16 + g;          // this lane's fragment rows: row0, row0+8
    float c[8][4] = {};
    #pragma unroll
    for (int ch = 0; ch < 4; ch++) {     // K chunks: row[0:64],row[64:128],col[0:64],col[64:128]
        if (ch) __syncthreads();
        { // gather A chunk row-major: 2 threads per edge, 8 x STS.128 each
            int e = tid >> 1, half = tid & 1;
            int src = sSrc[ch >> 1][e];
            const float4* hp = (const float4*)(g_h + src * 128 + (ch & 1) * 64) + half * 8;
            float4* dp = (float4*)(As + e * 68 + half * 32);
            #pragma unroll
            for (int j = 0; j < 8; j++) dp[j] = hp[j];
        }
        { // W1 fragment chunk (16KB)
            const float4* wp = (const float4*)(w1f + ch * 4096);
            float4* bp = (float4*)Bf;
            #pragma unroll
            for (int it = 0; it < 8; it++) bp[tid + it * 128] = wp[tid + it * 128];
        }
        __syncthreads();
        #pragma unroll
        for (int ks = 0; ks < 8; ks++) {
            const float* a0 = As + row0 * 68 + ks * 8;
            uint4 a = ld_a_frag(a0, a0 + 8 * 68, tig);
            #pragma unroll
            for (int nt = 0; nt < 8; nt++) {
                uint2 b = *(const uint2*)(Bf + ((ks * 8 + nt) * 32 + lane) * 2);
                mma_tf32(c[nt], a, b);
            }
        }
    }
    __syncthreads();   // all GEMM1 smem reads done

    // m1 epilogue: bias+silu -> Ms row-major (fp32; cvt happens at fragment load)
    #pragma unroll
    for (int nt = 0; nt < 8; nt++) {
        int n0 = nt * 8 + 2 * tig;
        float2 bn = *(const float2*)(b1 + n0);
        float2 vlo = make_float2(silu_f(c[nt][0] + bn.x), silu_f(c[nt][1] + bn.y));
        float2 vhi = make_float2(silu_f(c[nt][2] + bn.x), silu_f(c[nt][3] + bn.y));
        *(float2*)(As + row0 * 68 + n0)       = vlo;
        *(float2*)(As + (row0 + 8) * 68 + n0) = vhi;
    }
    { // W2 fragments (16KB)
        const float4* wp = (const float4*)w2f;
        float4* bp = (float4*)Bf;
        #pragma unroll
        for (int it = 0; it < 8; it++) bp[tid + it * 128] = wp[tid + it * 128];
    }
    #pragma unroll
    for (int nt = 0; nt < 8; nt++) {
        c[nt][0] = c[nt][1] = c[nt][2] = c[nt][3] = 0.f;
    }
    __syncthreads();

    // GEMM2: m2 = m1 @ W2, K=64
    #pragma unroll
    for (int ks = 0; ks < 8; ks++) {
        const float* a0 = As + row0 * 68 + ks * 8;
        uint4 a = ld_a_frag(a0, a0 + 8 * 68, tig);
        #pragma unroll
        for (int nt = 0; nt < 8; nt++) {
            uint2 b = *(const uint2*)(Bf + ((ks * 8 + nt) * 32 + lane) * 2);
            mma_tf32(c[nt], a, b);
        }
    }

    // final epilogue: bias+silu, scatter-add to g_agg[row]
    int dst0 = sSrc[0][row0], dst1 = sSrc[0][row0 + 8];
    #pragma unroll
    for (int nt = 0; nt < 8; nt++) {
        int n0 = nt * 8 + 2 * tig;
        float2 bn = *(const float2*)(b2 + n0);
        red_add_v2(g_agg + dst0 * 64 + n0, silu_f(c[nt][0] + bn.x), silu_f(c[nt][1] + bn.y));
        red_add_v2(g_agg + dst1 * 64 + n0, silu_f(c[nt][2] + bn.x), silu_f(c[nt][3] + bn.y));
    }
}

// ---------------------------------------------------------------------------
// node kernel (fp32): upd = silu([h, C*agg] @ W1 + b1) @ W2 + b2 ; if mask: h += upd
__global__ void __launch_bounds__(256) node_kernel(
    const float* __restrict__ W1, const float* __restrict__ b1,
    const float* __restrict__ W2, const float* __restrict__ b2,
    const int* __restrict__ mask, float C)
{
    extern __shared__ float sm[];
    float* As = sm;                 // 64*36
    float* Bs = sm + 64 * 36;       // 64*128
    float* Ts = Bs + 64 * 128;      // 32*128
    int tid = threadIdx.x;
    int tx = tid & 31, ty = tid >> 5;
    int n0 = blockIdx.x * 32;

    float acc[4][4] = {};
    #pragma unroll
    for (int ch = 0; ch < 3; ch++) {        // K=192: h[0:64], h[64:128], C*agg[0:64]
        __syncthreads();
        {
            int n = tid >> 3, kk = tid & 7;
            int node = n0 + n;
            #pragma unroll
            for (int it = 0; it < 2; it++) {
                int k4 = kk + it * 8;
                float4 v = make_float4(0.f, 0.f, 0.f, 0.f);
                if (node < N_NODES) {
                    if (ch < 2) v = ((const float4*)(g_h + node * 128 + ch * 64))[k4];
                    else {
                        v = ((const float4*)(g_agg + node * 64))[k4];
                        v.x *= C; v.y *= C; v.z *= C; v.w *= C;
                    }
                }
                As[(k4*4+0)*36 + n] = v.x; As[(k4*4+1)*36 + n] = v.y;
                As[(k4*4+2)*36 + n] = v.z; As[(k4*4+3)*36 + n] = v.w;
            }
        }
        {
            const float4* wp = (const float4*)(W1 + ch * 64 * 128);
            float4* bp = (float4*)Bs;
            #pragma unroll
            for (int it = 0; it < 8; it++) bp[tid + it * 256] = wp[tid + it * 256];
        }
        __syncthreads();
        #pragma unroll
        for (int k = 0; k < 64; k++) {
            float4 a  = *(const float4*)(As + k * 36 + ty * 4);
            float4 bb = *(const float4*)(Bs + k * 128 + tx * 4);
            FMA16(a, bb, acc);
        }
    }

    float4 bias1 = *(const float4*)(b1 + tx * 4);
    #pragma unroll
    for (int i = 0; i < 4; i++) {
        float4 v;
        v.x = silu_f(acc[i][0] + bias1.x);
        v.y = silu_f(acc[i][1] + bias1.y);
        v.z = silu_f(acc[i][2] + bias1.z);
        v.w = silu_f(acc[i][3] + bias1.w);
        *(float4*)(Ts + (ty * 4 + i) * 128 + tx * 4) = v;
    }

    float acc2[4][4] = {};
    #pragma unroll
    for (int ch = 0; ch < 2; ch++) {        // K=128
        __syncthreads();
        {
            const float4* wp = (const float4*)(W2 + ch * 64 * 128);
            float4* bp = (float4*)Bs;
            #pragma unroll
            for (int it = 0; it < 8; it++) bp[tid + it * 256] = wp[tid + it * 256];
        }
        __syncthreads();
        #pragma unroll
        for (int k = 0; k < 64; k++) {
            float4 bb = *(const float4*)(Bs + k * 128 + tx * 4);
            #pragma unroll
            for (int i = 0; i < 4; i++) {
                float a = Ts[(ty * 4 + i) * 128 + ch * 64 + k];
                acc2[i][0] += a * bb.x; acc2[i][1] += a * bb.y;
                acc2[i][2] += a * bb.z; acc2[i][3] += a * bb.w;
            }
        }
    }

    float4 bias2 = *(const float4*)(b2 + tx * 4);
    #pragma unroll
    for (int i = 0; i < 4; i++) {
        int node = n0 + ty * 4 + i;
        if (node < N_NODES && mask[node] != 0) {
            float4* hp = (float4*)(g_h + node * 128) + tx;
            float4 o = *hp;
            o.x += acc2[i][0] + bias2.x;
            o.y += acc2[i][1] + bias2.y;
            o.z += acc2[i][2] + bias2.z;
            o.w += acc2[i][3] + bias2.w;
            *hp = o;
        }
    }
}

// ---------------------------------------------------------------------------
// emb_out: out[N,64] = g_h[N,128] @ W[128,64] + b  (fp32 scalar)
__global__ void __launch_bounds__(256) emb_out_kernel(
    const float* __restrict__ W, const float* __restrict__ b, float* __restrict__ out)
{
    __shared__ float As[64 * 68];
    __shared__ float Bs[64 * 64];
    int tid = threadIdx.x;
    int tx = tid & 15, ty = tid >> 4;
    int n0 = blockIdx.x * 64;

    float acc[4][4] = {};
    #pragma unroll
    for (int ch = 0; ch < 2; ch++) {
        if (ch) __syncthreads();
        {
            int n = tid >> 2, kk = tid & 3;
            int node = n0 + n;
            #pragma unroll
            for (int it = 0; it < 4; it++) {
                int k4 = kk + it * 4;
                float4 v = make_float4(0.f, 0.f, 0.f, 0.f);
                if (node < N_NODES) v = ((const float4*)(g_h + node * 128 + ch * 64))[k4];
                As[(k4*4+0)*68 + n] = v.x; As[(k4*4+1)*68 + n] = v.y;
                As[(k4*4+2)*68 + n] = v.z; As[(k4*4+3)*68 + n] = v.w;
            }
        }
        {
            const float4* wp = (const float4*)(W + ch * 64 * 64);
            float4* bp = (float4*)Bs;
            #pragma unroll
            for (int it = 0; it < 4; it++) bp[tid + it * 256] = wp[tid + it * 256];
        }
        __syncthreads();
        #pragma unroll
        for (int k = 0; k < 64; k++) {
            float4 a  = *(const float4*)(As + k * 68 + ty * 4);
            float4 bb = *(const float4*)(Bs + k * 64 + tx * 4);
            FMA16(a, bb, acc);
        }
    }
    float4 bias = *(const float4*)(b + tx * 4);
    #pragma unroll
    for (int i = 0; i < 4; i++) {
        int node = n0 + ty * 4 + i;
        if (node < N_NODES) {
            float4 v = make_float4(acc[i][0]+bias.x, acc[i][1]+bias.y,
                                   acc[i][2]+bias.z, acc[i][3]+bias.w);
            *((float4*)(out + node * 64) + tx) = v;
        }
    }
}

// ---------------------------------------------------------------------------
extern "C" void kernel_launch(void* const* d_in, const int* in_sizes, int n_in,
                              void* d_out, int out_size)
{
    (void)in_sizes; (void)n_in; (void)out_size;
    const float* h0     = (const float*)d_in[0];
    const int*   ea     = (const int*)d_in[1];      // [2, E]
    const int*   ebp    = (const int*)d_in[2];      // [2, E]
    const int*   ma     = (const int*)d_in[3];      // bool -> int32
    const int*   mb     = (const int*)d_in[4];      // bool -> int32
    const float* w_in   = (const float*)d_in[5];
    const float* b_in   = (const float*)d_in[6];
    const float* w_out  = (const float*)d_in[7];
    const float* b_out  = (const float*)d_in[8];
    const float* ew1    = (const float*)d_in[9];    // [4,256,64]
    const float* eb1    = (const float*)d_in[10];   // [4,64]
    const float* ew2    = (const float*)d_in[11];   // [4,64,64]
    const float* eb2    = (const float*)d_in[12];   // [4,64]
    const float* nw1    = (const float*)d_in[13];   // [4,192,128]
    const float* nb1    = (const float*)d_in[14];   // [4,128]
    const float* nw2    = (const float*)d_in[15];   // [4,128,128]
    const float* nb2    = (const float*)d_in[16];   // [4,128]
    float*       out    = (float*)d_out;

    const int NODE_SMEM = (64 * 36 + 64 * 128 + 32 * 128) * (int)sizeof(float); // 58368
    (void)cudaFuncSetAttribute(node_kernel, cudaFuncAttributeMaxDynamicSharedMemorySize, NODE_SMEM);

    float* w1frag_base; cudaGetSymbolAddress((void**)&w1frag_base, g_w1frag);
    float* w2frag_base; cudaGetSymbolAddress((void**)&w2frag_base, g_w2frag);

    prep_wfrag_kernel<<<320, 256>>>(ew1, ew2);          // 81920 elements
    emb_in_kernel<<<(N_NODES + 31) / 32, 256>>>(h0, w_in, b_in);

    for (int l = 0; l < N_LAYERS; l++) {
        const int* er = (l & 1) ? ebp : ea;
        const int* m  = (l & 1) ? mb : ma;
        float C = (l & 1) ? (2.0f / 64.0f) : 1.0f;

        zero_agg_kernel<<<(N_NODES * EH / 4) / 256, 256>>>();
        edge_kernel_tc<<<E_TOTAL / 64, 128>>>(
            er, er + E_TOTAL,
            w1frag_base + l * 16384, eb1 + l * 64,
            w2frag_base + l * 4096,  eb2 + l * 64);
        node_kernel<<<(N_NODES + 31) / 32, 256, NODE_SMEM>>>(
            nw1 + l * 192 * 128, nb1 + l * 128,
            nw2 + l * 128 * 128, nb2 + l * 128, m, C);
    }

    emb_out_kernel<<<(N_NODES + 63) / 64, 256>>>(w_out, b_out, out);
}

// round 8
// speedup vs baseline: 3.8695x; 1.7415x over previous
#include <cuda_runtime.h>
#include <cuda_bf16.h>

#define N_NODES  50000
#define HID      128
#define EH       64
#define E_TOTAL  800000
#define N_LAYERS 4

typedef unsigned int uint;

// Persistent scratch (allowed: __device__ globals, no runtime alloc)
__device__ __align__(256) float g_h[N_NODES * HID];            // fp32 node features
__device__ __align__(256) __nv_bfloat16 g_hb[N_NODES * HID];   // bf16 mirror for edge gathers
__device__ __align__(256) float g_agg[N_NODES * EH];           // message accumulators
// bf16 fragment-ordered edge weights: [l][ch][ks][nt][lane][reg] (bf16x2 per uint)
__device__ __align__(256) uint g_w1f[4 * 4 * 4 * 8 * 32 * 2];  // 32768
__device__ __align__(256) uint g_w2f[4 * 4 * 8 * 32 * 2];      // 8192

__device__ __forceinline__ float silu_f(float x) {
    return x * (1.0f / (1.0f + __expf(-x)));
}
__device__ __forceinline__ void red_add_v2(float* p, float x, float y) {
    asm volatile("red.global.add.v2.f32 [%0], {%1,%2};" :: "l"(p), "f"(x), "f"(y) : "memory");
}
__device__ __forceinline__ uint smem_u32(const void* p) {
    return (uint)__cvta_generic_to_shared(p);
}
__device__ __forceinline__ void ldsm_x4(uint& r0, uint& r1, uint& r2, uint& r3, uint addr) {
    asm volatile("ldmatrix.sync.aligned.m8n8.x4.shared.b16 {%0,%1,%2,%3}, [%4];"
                 : "=r"(r0), "=r"(r1), "=r"(r2), "=r"(r3) : "r"(addr));
}
__device__ __forceinline__ void mma_bf16(float c[4], uint a0, uint a1, uint a2, uint a3,
                                         uint b0, uint b1) {
    asm("mma.sync.aligned.m16n8k16.row.col.f32.bf16.bf16.f32 "
        "{%0,%1,%2,%3},{%4,%5,%6,%7},{%8,%9},{%0,%1,%2,%3};"
        : "+f"(c[0]), "+f"(c[1]), "+f"(c[2]), "+f"(c[3])
        : "r"(a0), "r"(a1), "r"(a2), "r"(a3), "r"(b0), "r"(b1));
}
__device__ __forceinline__ uint pack_bf16x2(float lo, float hi) {
    __nv_bfloat162 p = __floats2bfloat162_rn(lo, hi);
    return *(uint*)&p;
}

#define FMA16(A4, B4, ACC) do { \
    ACC[0][0] += A4.x*B4.x; ACC[0][1] += A4.x*B4.y; ACC[0][2] += A4.x*B4.z; ACC[0][3] += A4.x*B4.w; \
    ACC[1][0] += A4.y*B4.x; ACC[1][1] += A4.y*B4.y; ACC[1][2] += A4.y*B4.z; ACC[1][3] += A4.y*B4.w; \
    ACC[2][0] += A4.z*B4.x; ACC[2][1] += A4.z*B4.y; ACC[2][2] += A4.z*B4.z; ACC[2][3] += A4.z*B4.w; \
    ACC[3][0] += A4.w*B4.x; ACC[3][1] += A4.w*B4.y; ACC[3][2] += A4.w*B4.z; ACC[3][3] += A4.w*B4.w; \
} while(0)

// ---------------------------------------------------------------------------
__global__ void zero_agg_kernel() {
    int i = blockIdx.x * blockDim.x + threadIdx.x;
    ((float4*)g_agg)[i] = make_float4(0.f, 0.f, 0.f, 0.f);
}

// ---------------------------------------------------------------------------
// Build bf16 fragment-ordered edge weights for mma.m16n8k16.row.col.
// B fragment: reg r of lane (g,tig) = W[kbase + r*8 + 2*tig .. +1][n = nt*8 + g]
__global__ void __launch_bounds__(256) prep_wfrag_bf(
    const float* __restrict__ ew1, const float* __restrict__ ew2)
{
    int i = blockIdx.x * 256 + threadIdx.x;     // 40960 total
    if (i < 32768) {
        int reg = i & 1, lane = (i >> 1) & 31, nt = (i >> 6) & 7,
            ks = (i >> 9) & 3, ch = (i >> 11) & 3, l = i >> 13;
        int g = lane >> 2, tig = lane & 3;
        int k = ch * 64 + ks * 16 + reg * 8 + 2 * tig;
        int n = nt * 8 + g;
        const float* base = ew1 + (l * 256 + k) * 64 + n;
        g_w1f[i] = pack_bf16x2(base[0], base[64]);
    } else {
        int j = i - 32768;
        int reg = j & 1, lane = (j >> 1) & 31, nt = (j >> 6) & 7,
            ks = (j >> 9) & 3, l = j >> 11;
        int g = lane >> 2, tig = lane & 3;
        int k = ks * 16 + reg * 8 + 2 * tig;
        int n = nt * 8 + g;
        const float* base = ew2 + (l * 64 + k) * 64 + n;
        g_w2f[j] = pack_bf16x2(base[0], base[64]);
    }
}

// ---------------------------------------------------------------------------
// emb_in: g_h[N,128] = x[N,64] @ W[64,128] + b ; also writes bf16 mirror
__global__ void __launch_bounds__(256) emb_in_kernel(
    const float* __restrict__ x, const float* __restrict__ W, const float* __restrict__ b)
{
    __shared__ float As[64 * 36];
    __shared__ float Bs[64 * 128];
    int tid = threadIdx.x;
    int tx = tid & 31, ty = tid >> 5;
    int n0 = blockIdx.x * 32;

    {
        int n = tid >> 3, kk = tid & 7;
        int node = n0 + n;
        #pragma unroll
        for (int it = 0; it < 2; it++) {
            int k4 = kk + it * 8;
            float4 v = make_float4(0.f, 0.f, 0.f, 0.f);
            if (node < N_NODES) v = ((const float4*)(x + node * 64))[k4];
            As[(k4*4+0)*36 + n] = v.x; As[(k4*4+1)*36 + n] = v.y;
            As[(k4*4+2)*36 + n] = v.z; As[(k4*4+3)*36 + n] = v.w;
        }
    }
    {
        const float4* wp = (const float4*)W;
        float4* bp = (float4*)Bs;
        #pragma unroll
        for (int it = 0; it < 8; it++) bp[tid + it * 256] = wp[tid + it * 256];
    }
    __syncthreads();

    float acc[4][4] = {};
    #pragma unroll
    for (int k = 0; k < 64; k++) {
        float4 a  = *(const float4*)(As + k * 36 + ty * 4);
        float4 bb = *(const float4*)(Bs + k * 128 + tx * 4);
        FMA16(a, bb, acc);
    }
    float4 bias = *(const float4*)(b + tx * 4);
    #pragma unroll
    for (int i = 0; i < 4; i++) {
        int node = n0 + ty * 4 + i;
        if (node < N_NODES) {
            float4 v = make_float4(acc[i][0]+bias.x, acc[i][1]+bias.y,
                                   acc[i][2]+bias.z, acc[i][3]+bias.w);
            *((float4*)(g_h + node * 128) + tx) = v;
            uint2 pk;
            pk.x = pack_bf16x2(v.x, v.y);
            pk.y = pack_bf16x2(v.z, v.w);
            *(uint2*)(g_hb + node * 128 + tx * 4) = pk;
        }
    }
}

// ---------------------------------------------------------------------------
// edge kernel (bf16 tensor-core): 64 edges/block, 128 threads (4 warps).
// A staged row-major bf16 (stride 72 -> 144B rows, ldmatrix conflict-free).
// mma.m16n8k16: GEMM1 K=256 (4 chunks x 4 ksteps), GEMM2 K=64 (4 ksteps).
__global__ void __launch_bounds__(128) edge_kernel_bf(
    const int* __restrict__ erow, const int* __restrict__ ecol,
    const uint* __restrict__ w1f, const float* __restrict__ b1,
    const uint* __restrict__ w2f, const float* __restrict__ b2)
{
    __shared__ int sSrc[2][64];
    __shared__ __align__(16) __nv_bfloat16 As[64 * 72];  // reused for m1
    __shared__ uint Bf[2048];     // [ks(4)][nt(8)][lane(32)][reg(2)]
    int tid = threadIdx.x;
    int lane = tid & 31, w = tid >> 5;
    int g = lane >> 2, tig = lane & 3;
    int e0 = blockIdx.x * 64;

    if (tid < 64) sSrc[0][tid]      = erow[e0 + tid];
    else          sSrc[1][tid - 64] = ecol[e0 + tid - 64];
    __syncthreads();

    int row0 = w * 16 + g;
    // ldmatrix x4: lanes 0-15 -> rows (w*16+lane&15) col 0; lanes 16-31 -> same rows col 8
    uint a_addr = smem_u32(As) + (uint)((w * 16 + (lane & 15)) * 144 + (lane >> 4) * 16);

    float c[8][4] = {};
    #pragma unroll
    for (int ch = 0; ch < 4; ch++) {   // K chunks: row[0:64],row[64:128],col[0:64],col[64:128]
        if (ch) __syncthreads();
        {   // gather A chunk: 2 threads/edge, 4 x STS.128 each (64B)
            int e = tid >> 1, half = tid & 1;
            int src = sSrc[ch >> 1][e];
            const uint4* hp = (const uint4*)(g_hb + src * 128 + (ch & 1) * 64) + half * 4;
            uint4* dp = (uint4*)(As + e * 72 + half * 32);
            dp[0] = hp[0]; dp[1] = hp[1]; dp[2] = hp[2]; dp[3] = hp[3];
        }
        {   // W1 fragment chunk: 2048 uints = 8KB
            const uint4* wp = (const uint4*)(w1f + ch * 2048);
            uint4* bp = (uint4*)Bf;
            #pragma unroll
            for (int it = 0; it < 4; it++) bp[tid + it * 128] = wp[tid + it * 128];
        }
        __syncthreads();
        #pragma unroll
        for (int ks = 0; ks < 4; ks++) {
            uint a0, a1, a2, a3;
            ldsm_x4(a0, a1, a2, a3, a_addr + ks * 32);
            #pragma unroll
            for (int nt = 0; nt < 8; nt++) {
                uint2 b = *(const uint2*)(Bf + ((ks * 8 + nt) * 32 + lane) * 2);
                mma_bf16(c[nt], a0, a1, a2, a3, b.x, b.y);
            }
        }
    }
    __syncthreads();   // all GEMM1 smem reads done

    // m1 epilogue: bias+silu -> As (bf16, row-major, same stride)
    #pragma unroll
    for (int nt = 0; nt < 8; nt++) {
        int n0 = nt * 8 + 2 * tig;
        float2 bn = *(const float2*)(b1 + n0);
        *(uint*)(As + row0 * 72 + n0) =
            pack_bf16x2(silu_f(c[nt][0] + bn.x), silu_f(c[nt][1] + bn.y));
        *(uint*)(As + (row0 + 8) * 72 + n0) =
            pack_bf16x2(silu_f(c[nt][2] + bn.x), silu_f(c[nt][3] + bn.y));
    }
    {   // W2 fragments: 2048 uints
        const uint4* wp = (const uint4*)w2f;
        uint4* bp = (uint4*)Bf;
        #pragma unroll
        for (int it = 0; it < 4; it++) bp[tid + it * 128] = wp[tid + it * 128];
    }
    #pragma unroll
    for (int nt = 0; nt < 8; nt++) { c[nt][0] = c[nt][1] = c[nt][2] = c[nt][3] = 0.f; }
    __syncthreads();

    // GEMM2: m2 = m1 @ W2, K=64
    #pragma unroll
    for (int ks = 0; ks < 4; ks++) {
        uint a0, a1, a2, a3;
        ldsm_x4(a0, a1, a2, a3, a_addr + ks * 32);
        #pragma unroll
        for (int nt = 0; nt < 8; nt++) {
            uint2 b = *(const uint2*)(Bf + ((ks * 8 + nt) * 32 + lane) * 2);
            mma_bf16(c[nt], a0, a1, a2, a3, b.x, b.y);
        }
    }

    // final epilogue: bias+silu, scatter-add
    int dst0 = sSrc[0][row0], dst1 = sSrc[0][row0 + 8];
    #pragma unroll
    for (int nt = 0; nt < 8; nt++) {
        int n0 = nt * 8 + 2 * tig;
        float2 bn = *(const float2*)(b2 + n0);
        red_add_v2(g_agg + dst0 * 64 + n0, silu_f(c[nt][0] + bn.x), silu_f(c[nt][1] + bn.y));
        red_add_v2(g_agg + dst1 * 64 + n0, silu_f(c[nt][2] + bn.x), silu_f(c[nt][3] + bn.y));
    }
}

// ---------------------------------------------------------------------------
// node kernel (fp32): upd = silu([h, C*agg] @ W1 + b1) @ W2 + b2 ; if mask: h += upd
// Updates both g_h and the bf16 mirror for masked nodes.
__global__ void __launch_bounds__(256) node_kernel(
    const float* __restrict__ W1, const float* __restrict__ b1,
    const float* __restrict__ W2, const float* __restrict__ b2,
    const int* __restrict__ mask, float C)
{
    extern __shared__ float sm[];
    float* As = sm;                 // 64*36
    float* Bs = sm + 64 * 36;       // 64*128
    float* Ts = Bs + 64 * 128;      // 32*128
    int tid = threadIdx.x;
    int tx = tid & 31, ty = tid >> 5;
    int n0 = blockIdx.x * 32;

    float acc[4][4] = {};
    #pragma unroll
    for (int ch = 0; ch < 3; ch++) {        // K=192: h[0:64], h[64:128], C*agg[0:64]
        __syncthreads();
        {
            int n = tid >> 3, kk = tid & 7;
            int node = n0 + n;
            #pragma unroll
            for (int it = 0; it < 2; it++) {
                int k4 = kk + it * 8;
                float4 v = make_float4(0.f, 0.f, 0.f, 0.f);
                if (node < N_NODES) {
                    if (ch < 2) v = ((const float4*)(g_h + node * 128 + ch * 64))[k4];
                    else {
                        v = ((const float4*)(g_agg + node * 64))[k4];
                        v.x *= C; v.y *= C; v.z *= C; v.w *= C;
                    }
                }
                As[(k4*4+0)*36 + n] = v.x; As[(k4*4+1)*36 + n] = v.y;
                As[(k4*4+2)*36 + n] = v.z; As[(k4*4+3)*36 + n] = v.w;
            }
        }
        {
            const float4* wp = (const float4*)(W1 + ch * 64 * 128);
            float4* bp = (float4*)Bs;
            #pragma unroll
            for (int it = 0; it < 8; it++) bp[tid + it * 256] = wp[tid + it * 256];
        }
        __syncthreads();
        #pragma unroll
        for (int k = 0; k < 64; k++) {
            float4 a  = *(const float4*)(As + k * 36 + ty * 4);
            float4 bb = *(const float4*)(Bs + k * 128 + tx * 4);
            FMA16(a, bb, acc);
        }
    }

    float4 bias1 = *(const float4*)(b1 + tx * 4);
    #pragma unroll
    for (int i = 0; i < 4; i++) {
        float4 v;
        v.x = silu_f(acc[i][0] + bias1.x);
        v.y = silu_f(acc[i][1] + bias1.y);
        v.z = silu_f(acc[i][2] + bias1.z);
        v.w = silu_f(acc[i][3] + bias1.w);
        *(float4*)(Ts + (ty * 4 + i) * 128 + tx * 4) = v;
    }

    float acc2[4][4] = {};
    #pragma unroll
    for (int ch = 0; ch < 2; ch++) {        // K=128
        __syncthreads();
        {
            const float4* wp = (const float4*)(W2 + ch * 64 * 128);
            float4* bp = (float4*)Bs;
            #pragma unroll
            for (int it = 0; it < 8; it++) bp[tid + it * 256] = wp[tid + it * 256];
        }
        __syncthreads();
        #pragma unroll
        for (int k = 0; k < 64; k++) {
            float4 bb = *(const float4*)(Bs + k * 128 + tx * 4);
            #pragma unroll
            for (int i = 0; i < 4; i++) {
                float a = Ts[(ty * 4 + i) * 128 + ch * 64 + k];
                acc2[i][0] += a * bb.x; acc2[i][1] += a * bb.y;
                acc2[i][2] += a * bb.z; acc2[i][3] += a * bb.w;
            }
        }
    }

    float4 bias2 = *(const float4*)(b2 + tx * 4);
    #pragma unroll
    for (int i = 0; i < 4; i++) {
        int node = n0 + ty * 4 + i;
        if (node < N_NODES && mask[node] != 0) {
            float4* hp = (float4*)(g_h + node * 128) + tx;
            float4 o = *hp;
            o.x += acc2[i][0] + bias2.x;
            o.y += acc2[i][1] + bias2.y;
            o.z += acc2[i][2] + bias2.z;
            o.w += acc2[i][3] + bias2.w;
            *hp = o;
            uint2 pk;
            pk.x = pack_bf16x2(o.x, o.y);
            pk.y = pack_bf16x2(o.z, o.w);
            *(uint2*)(g_hb + node * 128 + tx * 4) = pk;
        }
    }
}

// ---------------------------------------------------------------------------
// emb_out: out[N,64] = g_h[N,128] @ W[128,64] + b  (fp32 scalar)
__global__ void __launch_bounds__(256) emb_out_kernel(
    const float* __restrict__ W, const float* __restrict__ b, float* __restrict__ out)
{
    __shared__ float As[64 * 68];
    __shared__ float Bs[64 * 64];
    int tid = threadIdx.x;
    int tx = tid & 15, ty = tid >> 4;
    int n0 = blockIdx.x * 64;

    float acc[4][4] = {};
    #pragma unroll
    for (int ch = 0; ch < 2; ch++) {
        if (ch) __syncthreads();
        {
            int n = tid >> 2, kk = tid & 3;
            int node = n0 + n;
            #pragma unroll
            for (int it = 0; it < 4; it++) {
                int k4 = kk + it * 4;
                float4 v = make_float4(0.f, 0.f, 0.f, 0.f);
                if (node < N_NODES) v = ((const float4*)(g_h + node * 128 + ch * 64))[k4];
                As[(k4*4+0)*68 + n] = v.x; As[(k4*4+1)*68 + n] = v.y;
                As[(k4*4+2)*68 + n] = v.z; As[(k4*4+3)*68 + n] = v.w;
            }
        }
        {
            const float4* wp = (const float4*)(W + ch * 64 * 64);
            float4* bp = (float4*)Bs;
            #pragma unroll
            for (int it = 0; it < 4; it++) bp[tid + it * 256] = wp[tid + it * 256];
        }
        __syncthreads();
        #pragma unroll
        for (int k = 0; k < 64; k++) {
            float4 a  = *(const float4*)(As + k * 68 + ty * 4);
            float4 bb = *(const float4*)(Bs + k * 64 + tx * 4);
            FMA16(a, bb, acc);
        }
    }
    float4 bias = *(const float4*)(b + tx * 4);
    #pragma unroll
    for (int i = 0; i < 4; i++) {
        int node = n0 + ty * 4 + i;
        if (node < N_NODES) {
            float4 v = make_float4(acc[i][0]+bias.x, acc[i][1]+bias.y,
                                   acc[i][2]+bias.z, acc[i][3]+bias.w);
            *((float4*)(out + node * 64) + tx) = v;
        }
    }
}

// ---------------------------------------------------------------------------
extern "C" void kernel_launch(void* const* d_in, const int* in_sizes, int n_in,
                              void* d_out, int out_size)
{
    (void)in_sizes; (void)n_in; (void)out_size;
    const float* h0     = (const float*)d_in[0];
    const int*   ea     = (const int*)d_in[1];      // [2, E]
    const int*   ebp    = (const int*)d_in[2];      // [2, E]
    const int*   ma     = (const int*)d_in[3];      // bool -> int32
    const int*   mb     = (const int*)d_in[4];      // bool -> int32
    const float* w_in   = (const float*)d_in[5];
    const float* b_in   = (const float*)d_in[6];
    const float* w_out  = (const float*)d_in[7];
    const float* b_out  = (const float*)d_in[8];
    const float* ew1    = (const float*)d_in[9];    // [4,256,64]
    const float* eb1    = (const float*)d_in[10];   // [4,64]
    const float* ew2    = (const float*)d_in[11];   // [4,64,64]
    const float* eb2    = (const float*)d_in[12];   // [4,64]
    const float* nw1    = (const float*)d_in[13];   // [4,192,128]
    const float* nb1    = (const float*)d_in[14];   // [4,128]
    const float* nw2    = (const float*)d_in[15];   // [4,128,128]
    const float* nb2    = (const float*)d_in[16];   // [4,128]
    float*       out    = (float*)d_out;

    const int NODE_SMEM = (64 * 36 + 64 * 128 + 32 * 128) * (int)sizeof(float); // 58368
    (void)cudaFuncSetAttribute(node_kernel, cudaFuncAttributeMaxDynamicSharedMemorySize, NODE_SMEM);

    uint* w1f_base; cudaGetSymbolAddress((void**)&w1f_base, g_w1f);
    uint* w2f_base; cudaGetSymbolAddress((void**)&w2f_base, g_w2f);

    prep_wfrag_bf<<<160, 256>>>(ew1, ew2);          // 40960 elements
    emb_in_kernel<<<(N_NODES + 31) / 32, 256>>>(h0, w_in, b_in);

    for (int l = 0; l < N_LAYERS; l++) {
        const int* er = (l & 1) ? ebp : ea;
        const int* m  = (l & 1) ? mb : ma;
        float C = (l & 1) ? (2.0f / 64.0f) : 1.0f;

        zero_agg_kernel<<<(N_NODES * EH / 4) / 256, 256>>>();
        edge_kernel_bf<<<E_TOTAL / 64, 128>>>(
            er, er + E_TOTAL,
            w1f_base + l * 8192, eb1 + l * 64,
            w2f_base + l * 2048, eb2 + l * 64);
        node_kernel<<<(N_NODES + 31) / 32, 256, NODE_SMEM>>>(
            nw1 + l * 192 * 128, nb1 + l * 128,
            nw2 + l * 128 * 128, nb2 + l * 128, m, C);
    }

    emb_out_kernel<<<(N_NODES + 63) / 64, 256>>>(w_out, b_out, out);
}

// round 9
// speedup vs baseline: 3.8985x; 1.0075x over previous
#include <cuda_runtime.h>
#include <cuda_bf16.h>

#define N_NODES  50000
#define HID      128
#define EH       64
#define E_TOTAL  800000
#define N_LAYERS 4

typedef unsigned int uint;

// Persistent scratch (allowed: __device__ globals, no runtime alloc)
__device__ __align__(256) float g_h[N_NODES * HID];            // fp32 node features
__device__ __align__(256) __nv_bfloat16 g_hb[N_NODES * HID];   // bf16 mirror
__device__ __align__(256) float g_agg[N_NODES * EH];           // message accumulators
// bf16 fragment-ordered weights (built by prep kernel each launch)
__device__ __align__(256) uint g_w1f[4 * 4 * 4 * 8 * 32 * 2];    // edge W1: 32768
__device__ __align__(256) uint g_w2f[4 * 4 * 8 * 32 * 2];        // edge W2: 8192
__device__ __align__(256) uint g_nw1f[4 * 3 * 4 * 16 * 32 * 2];  // node W1: 49152
__device__ __align__(256) uint g_nw2f[4 * 8 * 16 * 32 * 2];      // node W2: 32768

__device__ __forceinline__ float silu_f(float x) {
    return x * (1.0f / (1.0f + __expf(-x)));
}
__device__ __forceinline__ void red_add_v2(float* p, float x, float y) {
    asm volatile("red.global.add.v2.f32 [%0], {%1,%2};" :: "l"(p), "f"(x), "f"(y) : "memory");
}
__device__ __forceinline__ uint smem_u32(const void* p) {
    return (uint)__cvta_generic_to_shared(p);
}
__device__ __forceinline__ void ldsm_x4(uint& r0, uint& r1, uint& r2, uint& r3, uint addr) {
    asm volatile("ldmatrix.sync.aligned.m8n8.x4.shared.b16 {%0,%1,%2,%3}, [%4];"
                 : "=r"(r0), "=r"(r1), "=r"(r2), "=r"(r3) : "r"(addr));
}
__device__ __forceinline__ void mma_bf16(float c[4], uint a0, uint a1, uint a2, uint a3,
                                         uint b0, uint b1) {
    asm("mma.sync.aligned.m16n8k16.row.col.f32.bf16.bf16.f32 "
        "{%0,%1,%2,%3},{%4,%5,%6,%7},{%8,%9},{%0,%1,%2,%3};"
        : "+f"(c[0]), "+f"(c[1]), "+f"(c[2]), "+f"(c[3])
        : "r"(a0), "r"(a1), "r"(a2), "r"(a3), "r"(b0), "r"(b1));
}
__device__ __forceinline__ uint pack_bf16x2(float lo, float hi) {
    __nv_bfloat162 p = __floats2bfloat162_rn(lo, hi);
    return *(uint*)&p;
}

#define FMA16(A4, B4, ACC) do { \
    ACC[0][0] += A4.x*B4.x; ACC[0][1] += A4.x*B4.y; ACC[0][2] += A4.x*B4.z; ACC[0][3] += A4.x*B4.w; \
    ACC[1][0] += A4.y*B4.x; ACC[1][1] += A4.y*B4.y; ACC[1][2] += A4.y*B4.z; ACC[1][3] += A4.y*B4.w; \
    ACC[2][0] += A4.z*B4.x; ACC[2][1] += A4.z*B4.y; ACC[2][2] += A4.z*B4.z; ACC[2][3] += A4.z*B4.w; \
    ACC[3][0] += A4.w*B4.x; ACC[3][1] += A4.w*B4.y; ACC[3][2] += A4.w*B4.z; ACC[3][3] += A4.w*B4.w; \
} while(0)

// ---------------------------------------------------------------------------
__global__ void zero_agg_kernel() {
    int i = blockIdx.x * blockDim.x + threadIdx.x;
    ((float4*)g_agg)[i] = make_float4(0.f, 0.f, 0.f, 0.f);
}

// ---------------------------------------------------------------------------
// Build all bf16 fragment-ordered weights (mma.m16n8k16.row.col B layout:
// reg r of lane (g,tig) = W[kbase + r*8 + 2*tig .. +1][n = nt*8 + g]).
__global__ void __launch_bounds__(256) prep_wfrag_bf(
    const float* __restrict__ ew1, const float* __restrict__ ew2,
    const float* __restrict__ nw1, const float* __restrict__ nw2)
{
    int i = blockIdx.x * 256 + threadIdx.x;     // 122880 total
    if (i < 32768) {            // edge W1: [l][ch4][ks4][nt8][lane][reg]
        int reg = i & 1, lane = (i >> 1) & 31, nt = (i >> 6) & 7,
            ks = (i >> 9) & 3, ch = (i >> 11) & 3, l = i >> 13;
        int g = lane >> 2, tig = lane & 3;
        int k = ch * 64 + ks * 16 + reg * 8 + 2 * tig;
        int n = nt * 8 + g;
        const float* base = ew1 + (l * 256 + k) * 64 + n;
        g_w1f[i] = pack_bf16x2(base[0], base[64]);
    } else if (i < 40960) {     // edge W2: [l][ks4][nt8][lane][reg]
        int j = i - 32768;
        int reg = j & 1, lane = (j >> 1) & 31, nt = (j >> 6) & 7,
            ks = (j >> 9) & 3, l = j >> 11;
        int g = lane >> 2, tig = lane & 3;
        int k = ks * 16 + reg * 8 + 2 * tig;
        int n = nt * 8 + g;
        const float* base = ew2 + (l * 64 + k) * 64 + n;
        g_w2f[j] = pack_bf16x2(base[0], base[64]);
    } else if (i < 90112) {     // node W1: [l][ch3][ks4][nt16][lane][reg]
        int j = i - 40960;
        int l = j / 12288, r = j % 12288;
        int ch = r >> 12, r2 = r & 4095;
        int ks = r2 >> 10, nt = (r2 >> 6) & 15, lane = (r2 >> 1) & 31, reg = r2 & 1;
        int g = lane >> 2, tig = lane & 3;
        int k = ch * 64 + ks * 16 + reg * 8 + 2 * tig;
        int n = nt * 8 + g;
        const float* base = nw1 + (l * 192 + k) * 128 + n;
        g_nw1f[j] = pack_bf16x2(base[0], base[128]);
    } else {                    // node W2: [l][ks8][nt16][lane][reg]
        int j = i - 90112;
        int l = j >> 13, r = j & 8191;
        int ks = r >> 10, nt = (r >> 6) & 15, lane = (r >> 1) & 31, reg = r & 1;
        int g = lane >> 2, tig = lane & 3;
        int k = ks * 16 + reg * 8 + 2 * tig;
        int n = nt * 8 + g;
        const float* base = nw2 + (l * 128 + k) * 128 + n;
        g_nw2f[j] = pack_bf16x2(base[0], base[128]);
    }
}

// ---------------------------------------------------------------------------
// emb_in: g_h[N,128] = x[N,64] @ W[64,128] + b ; also writes bf16 mirror
__global__ void __launch_bounds__(256) emb_in_kernel(
    const float* __restrict__ x, const float* __restrict__ W, const float* __restrict__ b)
{
    __shared__ float As[64 * 36];
    __shared__ float Bs[64 * 128];
    int tid = threadIdx.x;
    int tx = tid & 31, ty = tid >> 5;
    int n0 = blockIdx.x * 32;

    {
        int n = tid >> 3, kk = tid & 7;
        int node = n0 + n;
        #pragma unroll
        for (int it = 0; it < 2; it++) {
            int k4 = kk + it * 8;
            float4 v = make_float4(0.f, 0.f, 0.f, 0.f);
            if (node < N_NODES) v = ((const float4*)(x + node * 64))[k4];
            As[(k4*4+0)*36 + n] = v.x; As[(k4*4+1)*36 + n] = v.y;
            As[(k4*4+2)*36 + n] = v.z; As[(k4*4+3)*36 + n] = v.w;
        }
    }
    {
        const float4* wp = (const float4*)W;
        float4* bp = (float4*)Bs;
        #pragma unroll
        for (int it = 0; it < 8; it++) bp[tid + it * 256] = wp[tid + it * 256];
    }
    __syncthreads();

    float acc[4][4] = {};
    #pragma unroll
    for (int k = 0; k < 64; k++) {
        float4 a  = *(const float4*)(As + k * 36 + ty * 4);
        float4 bb = *(const float4*)(Bs + k * 128 + tx * 4);
        FMA16(a, bb, acc);
    }
    float4 bias = *(const float4*)(b + tx * 4);
    #pragma unroll
    for (int i = 0; i < 4; i++) {
        int node = n0 + ty * 4 + i;
        if (node < N_NODES) {
            float4 v = make_float4(acc[i][0]+bias.x, acc[i][1]+bias.y,
                                   acc[i][2]+bias.z, acc[i][3]+bias.w);
            *((float4*)(g_h + node * 128) + tx) = v;
            uint2 pk;
            pk.x = pack_bf16x2(v.x, v.y);
            pk.y = pack_bf16x2(v.z, v.w);
            *(uint2*)(g_hb + node * 128 + tx * 4) = pk;
        }
    }
}

// ---------------------------------------------------------------------------
// edge kernel (bf16 MMA): 128 edges/block, 128 threads, warp owns 32 rows (2 mtiles).
__global__ void __launch_bounds__(128) edge_kernel_bf(
    const int* __restrict__ erow, const int* __restrict__ ecol,
    const uint* __restrict__ w1f, const float* __restrict__ b1,
    const uint* __restrict__ w2f, const float* __restrict__ b2)
{
    __shared__ int sSrc[2][128];
    __shared__ __align__(16) __nv_bfloat16 As[128 * 72];  // reused for m1
    __shared__ uint Bf[2048];     // [ks4][nt8][lane][reg]
    int tid = threadIdx.x;
    int lane = tid & 31, w = tid >> 5;
    int g = lane >> 2, tig = lane & 3;
    int e0 = blockIdx.x * 128;

    sSrc[0][tid] = erow[e0 + tid];
    sSrc[1][tid] = ecol[e0 + tid];
    __syncthreads();

    uint a_base = smem_u32(As) + (uint)((w * 32 + (lane & 15)) * 144 + (lane >> 4) * 16);

    float c[2][8][4] = {};
    #pragma unroll
    for (int ch = 0; ch < 4; ch++) {   // K chunks: row[0:64],row[64:128],col[0:64],col[64:128]
        if (ch) __syncthreads();
        {   // gather A chunk: 1 thread/edge, 8 x STS.128
            int src = sSrc[ch >> 1][tid];
            const uint4* hp = (const uint4*)(g_hb + src * 128 + (ch & 1) * 64);
            uint4* dp = (uint4*)(As + tid * 72);
            #pragma unroll
            for (int j = 0; j < 8; j++) dp[j] = hp[j];
        }
        {   // W1 fragment chunk: 2048 uints = 8KB
            const uint4* wp = (const uint4*)(w1f + ch * 2048);
            uint4* bp = (uint4*)Bf;
            #pragma unroll
            for (int it = 0; it < 4; it++) bp[tid + it * 128] = wp[tid + it * 128];
        }
        __syncthreads();
        #pragma unroll
        for (int ks = 0; ks < 4; ks++) {
            uint a[2][4];
            ldsm_x4(a[0][0], a[0][1], a[0][2], a[0][3], a_base + ks * 32);
            ldsm_x4(a[1][0], a[1][1], a[1][2], a[1][3], a_base + 2304 + ks * 32);
            #pragma unroll
            for (int nt = 0; nt < 8; nt++) {
                uint2 b = *(const uint2*)(Bf + ((ks * 8 + nt) * 32 + lane) * 2);
                mma_bf16(c[0][nt], a[0][0], a[0][1], a[0][2], a[0][3], b.x, b.y);
                mma_bf16(c[1][nt], a[1][0], a[1][1], a[1][2], a[1][3], b.x, b.y);
            }
        }
    }
    __syncthreads();   // all GEMM1 smem reads done

    // m1 epilogue: bias+silu -> As (bf16, row-major)
    #pragma unroll
    for (int mt = 0; mt < 2; mt++) {
        int r = w * 32 + mt * 16 + g;
        #pragma unroll
        for (int nt = 0; nt < 8; nt++) {
            int n0 = nt * 8 + 2 * tig;
            float2 bn = *(const float2*)(b1 + n0);
            *(uint*)(As + r * 72 + n0) =
                pack_bf16x2(silu_f(c[mt][nt][0] + bn.x), silu_f(c[mt][nt][1] + bn.y));
            *(uint*)(As + (r + 8) * 72 + n0) =
                pack_bf16x2(silu_f(c[mt][nt][2] + bn.x), silu_f(c[mt][nt][3] + bn.y));
        }
    }
    {   // W2 fragments
        const uint4* wp = (const uint4*)w2f;
        uint4* bp = (uint4*)Bf;
        #pragma unroll
        for (int it = 0; it < 4; it++) bp[tid + it * 128] = wp[tid + it * 128];
    }
    #pragma unroll
    for (int mt = 0; mt < 2; mt++)
        #pragma unroll
        for (int nt = 0; nt < 8; nt++)
            c[mt][nt][0] = c[mt][nt][1] = c[mt][nt][2] = c[mt][nt][3] = 0.f;
    __syncthreads();

    // GEMM2: m2 = m1 @ W2, K=64
    #pragma unroll
    for (int ks = 0; ks < 4; ks++) {
        uint a[2][4];
        ldsm_x4(a[0][0], a[0][1], a[0][2], a[0][3], a_base + ks * 32);
        ldsm_x4(a[1][0], a[1][1], a[1][2], a[1][3], a_base + 2304 + ks * 32);
        #pragma unroll
        for (int nt = 0; nt < 8; nt++) {
            uint2 b = *(const uint2*)(Bf + ((ks * 8 + nt) * 32 + lane) * 2);
            mma_bf16(c[0][nt], a[0][0], a[0][1], a[0][2], a[0][3], b.x, b.y);
            mma_bf16(c[1][nt], a[1][0], a[1][1], a[1][2], a[1][3], b.x, b.y);
        }
    }

    // final epilogue: bias+silu, scatter-add
    #pragma unroll
    for (int mt = 0; mt < 2; mt++) {
        int r = w * 32 + mt * 16 + g;
        int dst0 = sSrc[0][r], dst1 = sSrc[0][r + 8];
        #pragma unroll
        for (int nt = 0; nt < 8; nt++) {
            int n0 = nt * 8 + 2 * tig;
            float2 bn = *(const float2*)(b2 + n0);
            red_add_v2(g_agg + dst0 * 64 + n0,
                       silu_f(c[mt][nt][0] + bn.x), silu_f(c[mt][nt][1] + bn.y));
            red_add_v2(g_agg + dst1 * 64 + n0,
                       silu_f(c[mt][nt][2] + bn.x), silu_f(c[mt][nt][3] + bn.y));
        }
    }
}

// ---------------------------------------------------------------------------
// node kernel (bf16 MMA): 64 nodes/block, 128 threads, warp owns 16 rows, N=128 (16 nt).
// GEMM1 K=192 (3 chunks: h lo, h hi, C*agg); GEMM2 K=128 (W2 in two halves).
// Residual + mask in fp32; updates g_h and bf16 mirror.
__global__ void __launch_bounds__(128) node_kernel_bf(
    const uint* __restrict__ w1f, const float* __restrict__ b1,
    const uint* __restrict__ w2f, const float* __restrict__ b2,
    const int* __restrict__ mask, float C)
{
    __shared__ __align__(16) __nv_bfloat16 As[64 * 72];    // A chunk
    __shared__ __align__(16) __nv_bfloat16 Ms[64 * 136];   // m1 [64][128], stride 136
    __shared__ uint Bf[4096];     // [ks4][nt16][lane][reg]
    int tid = threadIdx.x;
    int lane = tid & 31, w = tid >> 5;
    int g = lane >> 2, tig = lane & 3;
    int nblk = blockIdx.x * 64;
    int row0 = w * 16 + g;

    uint a_addr = smem_u32(As) + (uint)((w * 16 + (lane & 15)) * 144 + (lane >> 4) * 16);
    uint m_addr = smem_u32(Ms) + (uint)((w * 16 + (lane & 15)) * 272 + (lane >> 4) * 16);

    float c[16][4] = {};
    #pragma unroll
    for (int ch = 0; ch < 3; ch++) {
        if (ch) __syncthreads();
        {   // gather: 2 threads/node
            int e = tid >> 1, half = tid & 1;
            int node = nblk + e;
            if (ch < 2) {
                uint4* dp = (uint4*)(As + e * 72 + half * 32);
                if (node < N_NODES) {
                    const uint4* hp = (const uint4*)(g_hb + node * 128 + ch * 64) + half * 4;
                    dp[0] = hp[0]; dp[1] = hp[1]; dp[2] = hp[2]; dp[3] = hp[3];
                } else {
                    uint4 z = make_uint4(0, 0, 0, 0);
                    dp[0] = z; dp[1] = z; dp[2] = z; dp[3] = z;
                }
            } else {
                const float4* ap = (const float4*)(g_agg + node * 64) + half * 8;
                uint2* dp = (uint2*)(As + e * 72 + half * 32);
                #pragma unroll
                for (int j = 0; j < 8; j++) {
                    float4 v = (node < N_NODES) ? ap[j] : make_float4(0.f, 0.f, 0.f, 0.f);
                    uint2 pk;
                    pk.x = pack_bf16x2(v.x * C, v.y * C);
                    pk.y = pack_bf16x2(v.z * C, v.w * C);
                    dp[j] = pk;
                }
            }
        }
        {   // W1 chunk: 4096 uints = 16KB
            const uint4* wp = (const uint4*)(w1f + ch * 4096);
            uint4* bp = (uint4*)Bf;
            #pragma unroll
            for (int it = 0; it < 8; it++) bp[tid + it * 128] = wp[tid + it * 128];
        }
        __syncthreads();
        #pragma unroll
        for (int ks = 0; ks < 4; ks++) {
            uint a0, a1, a2, a3;
            ldsm_x4(a0, a1, a2, a3, a_addr + ks * 32);
            #pragma unroll
            for (int nt = 0; nt < 16; nt++) {
                uint2 b = *(const uint2*)(Bf + ((ks * 16 + nt) * 32 + lane) * 2);
                mma_bf16(c[nt], a0, a1, a2, a3, b.x, b.y);
            }
        }
    }
    __syncthreads();

    // m1 epilogue: bias+silu -> Ms (bf16)
    #pragma unroll
    for (int nt = 0; nt < 16; nt++) {
        int nn = nt * 8 + 2 * tig;
        float2 bn = *(const float2*)(b1 + nn);
        *(uint*)(Ms + row0 * 136 + nn) =
            pack_bf16x2(silu_f(c[nt][0] + bn.x), silu_f(c[nt][1] + bn.y));
        *(uint*)(Ms + (row0 + 8) * 136 + nn) =
            pack_bf16x2(silu_f(c[nt][2] + bn.x), silu_f(c[nt][3] + bn.y));
    }
    #pragma unroll
    for (int nt = 0; nt < 16; nt++) { c[nt][0] = c[nt][1] = c[nt][2] = c[nt][3] = 0.f; }

    // GEMM2: K=128, W2 fragments in two 16KB halves
    #pragma unroll
    for (int hf = 0; hf < 2; hf++) {
        __syncthreads();            // Ms visible (hf=0) / prior Bf reads done (hf=1)
        {
            const uint4* wp = (const uint4*)(w2f + hf * 4096);
            uint4* bp = (uint4*)Bf;
            #pragma unroll
            for (int it = 0; it < 8; it++) bp[tid + it * 128] = wp[tid + it * 128];
        }
        __syncthreads();
        #pragma unroll
        for (int ks = 0; ks < 4; ks++) {
            uint a0, a1, a2, a3;
            ldsm_x4(a0, a1, a2, a3, m_addr + (hf * 4 + ks) * 32);
            #pragma unroll
            for (int nt = 0; nt < 16; nt++) {
                uint2 b = *(const uint2*)(Bf + ((ks * 16 + nt) * 32 + lane) * 2);
                mma_bf16(c[nt], a0, a1, a2, a3, b.x, b.y);
            }
        }
    }

    // final: residual + mask (fp32), update g_h and mirror
    int node0 = nblk + row0, node1 = node0 + 8;
    int m0 = (node0 < N_NODES) ? mask[node0] : 0;
    int m1v = (node1 < N_NODES) ? mask[node1] : 0;
    #pragma unroll
    for (int nt = 0; nt < 16; nt++) {
        int nn = nt * 8 + 2 * tig;
        float2 bn = *(const float2*)(b2 + nn);
        if (m0) {
            float2 h = *(float2*)(g_h + node0 * 128 + nn);
            h.x += c[nt][0] + bn.x; h.y += c[nt][1] + bn.y;
            *(float2*)(g_h + node0 * 128 + nn) = h;
            *(uint*)(g_hb + node0 * 128 + nn) = pack_bf16x2(h.x, h.y);
        }
        if (m1v) {
            float2 h = *(float2*)(g_h + node1 * 128 + nn);
            h.x += c[nt][2] + bn.x; h.y += c[nt][3] + bn.y;
            *(float2*)(g_h + node1 * 128 + nn) = h;
            *(uint*)(g_hb + node1 * 128 + nn) = pack_bf16x2(h.x, h.y);
        }
    }
}

// ---------------------------------------------------------------------------
// emb_out: out[N,64] = g_h[N,128] @ W[128,64] + b  (fp32 scalar)
__global__ void __launch_bounds__(256) emb_out_kernel(
    const float* __restrict__ W, const float* __restrict__ b, float* __restrict__ out)
{
    __shared__ float As[64 * 68];
    __shared__ float Bs[64 * 64];
    int tid = threadIdx.x;
    int tx = tid & 15, ty = tid >> 4;
    int n0 = blockIdx.x * 64;

    float acc[4][4] = {};
    #pragma unroll
    for (int ch = 0; ch < 2; ch++) {
        if (ch) __syncthreads();
        {
            int n = tid >> 2, kk = tid & 3;
            int node = n0 + n;
            #pragma unroll
            for (int it = 0; it < 4; it++) {
                int k4 = kk + it * 4;
                float4 v = make_float4(0.f, 0.f, 0.f, 0.f);
                if (node < N_NODES) v = ((const float4*)(g_h + node * 128 + ch * 64))[k4];
                As[(k4*4+0)*68 + n] = v.x; As[(k4*4+1)*68 + n] = v.y;
                As[(k4*4+2)*68 + n] = v.z; As[(k4*4+3)*68 + n] = v.w;
            }
        }
        {
            const float4* wp = (const float4*)(W + ch * 64 * 64);
            float4* bp = (float4*)Bs;
            #pragma unroll
            for (int it = 0; it < 4; it++) bp[tid + it * 256] = wp[tid + it * 256];
        }
        __syncthreads();
        #pragma unroll
        for (int k = 0; k < 64; k++) {
            float4 a  = *(const float4*)(As + k * 68 + ty * 4);
            float4 bb = *(const float4*)(Bs + k * 64 + tx * 4);
            FMA16(a, bb, acc);
        }
    }
    float4 bias = *(const float4*)(b + tx * 4);
    #pragma unroll
    for (int i = 0; i < 4; i++) {
        int node = n0 + ty * 4 + i;
        if (node < N_NODES) {
            float4 v = make_float4(acc[i][0]+bias.x, acc[i][1]+bias.y,
                                   acc[i][2]+bias.z, acc[i][3]+bias.w);
            *((float4*)(out + node * 64) + tx) = v;
        }
    }
}

// ---------------------------------------------------------------------------
extern "C" void kernel_launch(void* const* d_in, const int* in_sizes, int n_in,
                              void* d_out, int out_size)
{
    (void)in_sizes; (void)n_in; (void)out_size;
    const float* h0     = (const float*)d_in[0];
    const int*   ea     = (const int*)d_in[1];      // [2, E]
    const int*   ebp    = (const int*)d_in[2];      // [2, E]
    const int*   ma     = (const int*)d_in[3];      // bool -> int32
    const int*   mb     = (const int*)d_in[4];      // bool -> int32
    const float* w_in   = (const float*)d_in[5];
    const float* b_in   = (const float*)d_in[6];
    const float* w_out  = (const float*)d_in[7];
    const float* b_out  = (const float*)d_in[8];
    const float* ew1    = (const float*)d_in[9];    // [4,256,64]
    const float* eb1    = (const float*)d_in[10];   // [4,64]
    const float* ew2    = (const float*)d_in[11];   // [4,64,64]
    const float* eb2    = (const float*)d_in[12];   // [4,64]
    const float* nw1    = (const float*)d_in[13];   // [4,192,128]
    const float* nb1    = (const float*)d_in[14];   // [4,128]
    const float* nw2    = (const float*)d_in[15];   // [4,128,128]
    const float* nb2    = (const float*)d_in[16];   // [4,128]
    float*       out    = (float*)d_out;

    uint* w1f_base;  cudaGetSymbolAddress((void**)&w1f_base,  g_w1f);
    uint* w2f_base;  cudaGetSymbolAddress((void**)&w2f_base,  g_w2f);
    uint* nw1f_base; cudaGetSymbolAddress((void**)&nw1f_base, g_nw1f);
    uint* nw2f_base; cudaGetSymbolAddress((void**)&nw2f_base, g_nw2f);

    prep_wfrag_bf<<<480, 256>>>(ew1, ew2, nw1, nw2);    // 122880 elements
    emb_in_kernel<<<(N_NODES + 31) / 32, 256>>>(h0, w_in, b_in);

    for (int l = 0; l < N_LAYERS; l++) {
        const int* er = (l & 1) ? ebp : ea;
        const int* m  = (l & 1) ? mb : ma;
        float C = (l & 1) ? (2.0f / 64.0f) : 1.0f;

        zero_agg_kernel<<<(N_NODES * EH / 4) / 256, 256>>>();
        edge_kernel_bf<<<E_TOTAL / 128, 128>>>(
            er, er + E_TOTAL,
            w1f_base + l * 8192, eb1 + l * 64,
            w2f_base + l * 2048, eb2 + l * 64);
        node_kernel_bf<<<(N_NODES + 63) / 64, 128>>>(
            nw1f_base + l * 12288, nb1 + l * 128,
            nw2f_base + l * 8192,  nb2 + l * 128, m, C);
    }

    emb_out_kernel<<<(N_NODES + 63) / 64, 256>>>(w_out, b_out, out);
}

// round 13
// speedup vs baseline: 4.8146x; 1.2350x over previous
#include <cuda_runtime.h>
#include <cuda_bf16.h>

#define N_NODES  50000
#define HID      128
#define EH       64
#define E_TOTAL  800000
#define N_LAYERS 4

typedef unsigned int uint;

// Persistent scratch (allowed: __device__ globals, no runtime alloc)
__device__ __align__(256) float g_h[N_NODES * HID];            // fp32 node features
__device__ __align__(256) __nv_bfloat16 g_hb[N_NODES * HID];   // bf16 mirror
__device__ __align__(256) float g_agg[N_NODES * EH];           // message accumulators
// bf16 fragment-ordered weights (built by prep kernel each launch)
__device__ __align__(256) uint g_w1f[4 * 4 * 4 * 8 * 32 * 2];    // edge W1: 32768
__device__ __align__(256) uint g_w2f[4 * 4 * 8 * 32 * 2];        // edge W2: 8192
__device__ __align__(256) uint g_nw1f[4 * 3 * 4 * 16 * 32 * 2];  // node W1: 49152
__device__ __align__(256) uint g_nw2f[4 * 8 * 16 * 32 * 2];      // node W2: 32768

__device__ __forceinline__ float silu_f(float x) {
    return x * (1.0f / (1.0f + __expf(-x)));
}
__device__ __forceinline__ void red_add_v2(float* p, float x, float y) {
    asm volatile("red.global.add.v2.f32 [%0], {%1,%2};" :: "l"(p), "f"(x), "f"(y) : "memory");
}
__device__ __forceinline__ uint smem_u32(const void* p) {
    return (uint)__cvta_generic_to_shared(p);
}
__device__ __forceinline__ void ldsm_x4(uint& r0, uint& r1, uint& r2, uint& r3, uint addr) {
    asm volatile("ldmatrix.sync.aligned.m8n8.x4.shared.b16 {%0,%1,%2,%3}, [%4];"
                 : "=r"(r0), "=r"(r1), "=r"(r2), "=r"(r3) : "r"(addr));
}
__device__ __forceinline__ void mma_bf16(float c[4], uint a0, uint a1, uint a2, uint a3,
                                         uint b0, uint b1) {
    asm("mma.sync.aligned.m16n8k16.row.col.f32.bf16.bf16.f32 "
        "{%0,%1,%2,%3},{%4,%5,%6,%7},{%8,%9},{%0,%1,%2,%3};"
        : "+f"(c[0]), "+f"(c[1]), "+f"(c[2]), "+f"(c[3])
        : "r"(a0), "r"(a1), "r"(a2), "r"(a3), "r"(b0), "r"(b1));
}
__device__ __forceinline__ uint pack_bf16x2(float lo, float hi) {
    __nv_bfloat162 p = __floats2bfloat162_rn(lo, hi);
    return *(uint*)&p;
}

#define FMA16(A4, B4, ACC) do { \
    ACC[0][0] += A4.x*B4.x; ACC[0][1] += A4.x*B4.y; ACC[0][2] += A4.x*B4.z; ACC[0][3] += A4.x*B4.w; \
    ACC[1][0] += A4.y*B4.x; ACC[1][1] += A4.y*B4.y; ACC[1][2] += A4.y*B4.z; ACC[1][3] += A4.y*B4.w; \
    ACC[2][0] += A4.z*B4.x; ACC[2][1] += A4.z*B4.y; ACC[2][2] += A4.z*B4.z; ACC[2][3] += A4.z*B4.w; \
    ACC[3][0] += A4.w*B4.x; ACC[3][1] += A4.w*B4.y; ACC[3][2] += A4.w*B4.z; ACC[3][3] += A4.w*B4.w; \
} while(0)

// ---------------------------------------------------------------------------
__global__ void zero_agg_kernel() {
    int i = blockIdx.x * blockDim.x + threadIdx.x;
    ((float4*)g_agg)[i] = make_float4(0.f, 0.f, 0.f, 0.f);
}

// ---------------------------------------------------------------------------
// Build all bf16 fragment-ordered weights (mma.m16n8k16.row.col B layout:
// reg r of lane (g,tig) = W[kbase + r*8 + 2*tig .. +1][n = nt*8 + g]).
__global__ void __launch_bounds__(256) prep_wfrag_bf(
    const float* __restrict__ ew1, const float* __restrict__ ew2,
    const float* __restrict__ nw1, const float* __restrict__ nw2)
{
    int i = blockIdx.x * 256 + threadIdx.x;     // 122880 total
    if (i < 32768) {            // edge W1: [l][ch4][ks4][nt8][lane][reg]
        int reg = i & 1, lane = (i >> 1) & 31, nt = (i >> 6) & 7,
            ks = (i >> 9) & 3, ch = (i >> 11) & 3, l = i >> 13;
        int g = lane >> 2, tig = lane & 3;
        int k = ch * 64 + ks * 16 + reg * 8 + 2 * tig;
        int n = nt * 8 + g;
        const float* base = ew1 + (l * 256 + k) * 64 + n;
        g_w1f[i] = pack_bf16x2(base[0], base[64]);
    } else if (i < 40960) {     // edge W2: [l][ks4][nt8][lane][reg]
        int j = i - 32768;
        int reg = j & 1, lane = (j >> 1) & 31, nt = (j >> 6) & 7,
            ks = (j >> 9) & 3, l = j >> 11;
        int g = lane >> 2, tig = lane & 3;
        int k = ks * 16 + reg * 8 + 2 * tig;
        int n = nt * 8 + g;
        const float* base = ew2 + (l * 64 + k) * 64 + n;
        g_w2f[j] = pack_bf16x2(base[0], base[64]);
    } else if (i < 90112) {     // node W1: [l][ch3][ks4][nt16][lane][reg]
        int j = i - 40960;
        int l = j / 12288, r = j % 12288;
        int ch = r >> 12, r2 = r & 4095;
        int ks = r2 >> 10, nt = (r2 >> 6) & 15, lane = (r2 >> 1) & 31, reg = r2 & 1;
        int g = lane >> 2, tig = lane & 3;
        int k = ch * 64 + ks * 16 + reg * 8 + 2 * tig;
        int n = nt * 8 + g;
        const float* base = nw1 + (l * 192 + k) * 128 + n;
        g_nw1f[j] = pack_bf16x2(base[0], base[128]);
    } else {                    // node W2: [l][ks8][nt16][lane][reg]
        int j = i - 90112;
        int l = j >> 13, r = j & 8191;
        int ks = r >> 10, nt = (r >> 6) & 15, lane = (r >> 1) & 31, reg = r & 1;
        int g = lane >> 2, tig = lane & 3;
        int k = ks * 16 + reg * 8 + 2 * tig;
        int n = nt * 8 + g;
        const float* base = nw2 + (l * 128 + k) * 128 + n;
        g_nw2f[j] = pack_bf16x2(base[0], base[128]);
    }
}

// ---------------------------------------------------------------------------
// emb_in: g_h[N,128] = x[N,64] @ W[64,128] + b ; also writes bf16 mirror
__global__ void __launch_bounds__(256) emb_in_kernel(
    const float* __restrict__ x, const float* __restrict__ W, const float* __restrict__ b)
{
    __shared__ float As[64 * 36];
    __shared__ float Bs[64 * 128];
    int tid = threadIdx.x;
    int tx = tid & 31, ty = tid >> 5;
    int n0 = blockIdx.x * 32;

    {
        int n = tid >> 3, kk = tid & 7;
        int node = n0 + n;
        #pragma unroll
        for (int it = 0; it < 2; it++) {
            int k4 = kk + it * 8;
            float4 v = make_float4(0.f, 0.f, 0.f, 0.f);
            if (node < N_NODES) v = ((const float4*)(x + node * 64))[k4];
            As[(k4*4+0)*36 + n] = v.x; As[(k4*4+1)*36 + n] = v.y;
            As[(k4*4+2)*36 + n] = v.z; As[(k4*4+3)*36 + n] = v.w;
        }
    }
    {
        const float4* wp = (const float4*)W;
        float4* bp = (float4*)Bs;
        #pragma unroll
        for (int it = 0; it < 8; it++) bp[tid + it * 256] = wp[tid + it * 256];
    }
    __syncthreads();

    float acc[4][4] = {};
    #pragma unroll
    for (int k = 0; k < 64; k++) {
        float4 a  = *(const float4*)(As + k * 36 + ty * 4);
        float4 bb = *(const float4*)(Bs + k * 128 + tx * 4);
        FMA16(a, bb, acc);
    }
    float4 bias = *(const float4*)(b + tx * 4);
    #pragma unroll
    for (int i = 0; i < 4; i++) {
        int node = n0 + ty * 4 + i;
        if (node < N_NODES) {
            float4 v = make_float4(acc[i][0]+bias.x, acc[i][1]+bias.y,
                                   acc[i][2]+bias.z, acc[i][3]+bias.w);
            *((float4*)(g_h + node * 128) + tx) = v;
            uint2 pk;
            pk.x = pack_bf16x2(v.x, v.y);
            pk.y = pack_bf16x2(v.z, v.w);
            *(uint2*)(g_hb + node * 128 + tx * 4) = pk;
        }
    }
}

// ---------------------------------------------------------------------------
// edge kernel (bf16 tensor-core, Round-8 config): 64 edges/block, 128 threads.
// A staged row-major bf16 (stride 72 -> 144B rows, ldmatrix conflict-free).
// mma.m16n8k16: GEMM1 K=256 (4 chunks x 4 ksteps), GEMM2 K=64 (4 ksteps).
__global__ void __launch_bounds__(128) edge_kernel_bf(
    const int* __restrict__ erow, const int* __restrict__ ecol,
    const uint* __restrict__ w1f, const float* __restrict__ b1,
    const uint* __restrict__ w2f, const float* __restrict__ b2)
{
    __shared__ int sSrc[2][64];
    __shared__ __align__(16) __nv_bfloat16 As[64 * 72];  // reused for m1
    __shared__ uint Bf[2048];     // [ks(4)][nt(8)][lane(32)][reg(2)]
    int tid = threadIdx.x;
    int lane = tid & 31, w = tid >> 5;
    int g = lane >> 2, tig = lane & 3;
    int e0 = blockIdx.x * 64;

    if (tid < 64) sSrc[0][tid]      = erow[e0 + tid];
    else          sSrc[1][tid - 64] = ecol[e0 + tid - 64];
    __syncthreads();

    int row0 = w * 16 + g;
    uint a_addr = smem_u32(As) + (uint)((w * 16 + (lane & 15)) * 144 + (lane >> 4) * 16);

    float c[8][4] = {};
    #pragma unroll
    for (int ch = 0; ch < 4; ch++) {   // K chunks: row[0:64],row[64:128],col[0:64],col[64:128]
        if (ch) __syncthreads();
        {   // gather A chunk: 2 threads/edge, 4 x STS.128 each (64B)
            int e = tid >> 1, half = tid & 1;
            int src = sSrc[ch >> 1][e];
            const uint4* hp = (const uint4*)(g_hb + src * 128 + (ch & 1) * 64) + half * 4;
            uint4* dp = (uint4*)(As + e * 72 + half * 32);
            dp[0] = hp[0]; dp[1] = hp[1]; dp[2] = hp[2]; dp[3] = hp[3];
        }
        {   // W1 fragment chunk: 2048 uints = 8KB
            const uint4* wp = (const uint4*)(w1f + ch * 2048);
            uint4* bp = (uint4*)Bf;
            #pragma unroll
            for (int it = 0; it < 4; it++) bp[tid + it * 128] = wp[tid + it * 128];
        }
        __syncthreads();
        #pragma unroll
        for (int ks = 0; ks < 4; ks++) {
            uint a0, a1, a2, a3;
            ldsm_x4(a0, a1, a2, a3, a_addr + ks * 32);
            #pragma unroll
            for (int nt = 0; nt < 8; nt++) {
                uint2 b = *(const uint2*)(Bf + ((ks * 8 + nt) * 32 + lane) * 2);
                mma_bf16(c[nt], a0, a1, a2, a3, b.x, b.y);
            }
        }
    }
    __syncthreads();   // all GEMM1 smem reads done

    // m1 epilogue: bias+silu -> As (bf16, row-major, same stride)
    #pragma unroll
    for (int nt = 0; nt < 8; nt++) {
        int n0 = nt * 8 + 2 * tig;
        float2 bn = *(const float2*)(b1 + n0);
        *(uint*)(As + row0 * 72 + n0) =
            pack_bf16x2(silu_f(c[nt][0] + bn.x), silu_f(c[nt][1] + bn.y));
        *(uint*)(As + (row0 + 8) * 72 + n0) =
            pack_bf16x2(silu_f(c[nt][2] + bn.x), silu_f(c[nt][3] + bn.y));
    }
    {   // W2 fragments: 2048 uints
        const uint4* wp = (const uint4*)w2f;
        uint4* bp = (uint4*)Bf;
        #pragma unroll
        for (int it = 0; it < 4; it++) bp[tid + it * 128] = wp[tid + it * 128];
    }
    #pragma unroll
    for (int nt = 0; nt < 8; nt++) { c[nt][0] = c[nt][1] = c[nt][2] = c[nt][3] = 0.f; }
    __syncthreads();

    // GEMM2: m2 = m1 @ W2, K=64
    #pragma unroll
    for (int ks = 0; ks < 4; ks++) {
        uint a0, a1, a2, a3;
        ldsm_x4(a0, a1, a2, a3, a_addr + ks * 32);
        #pragma unroll
        for (int nt = 0; nt < 8; nt++) {
            uint2 b = *(const uint2*)(Bf + ((ks * 8 + nt) * 32 + lane) * 2);
            mma_bf16(c[nt], a0, a1, a2, a3, b.x, b.y);
        }
    }

    // final epilogue: bias+silu, scatter-add
    int dst0 = sSrc[0][row0], dst1 = sSrc[0][row0 + 8];
    #pragma unroll
    for (int nt = 0; nt < 8; nt++) {
        int n0 = nt * 8 + 2 * tig;
        float2 bn = *(const float2*)(b2 + n0);
        red_add_v2(g_agg + dst0 * 64 + n0, silu_f(c[nt][0] + bn.x), silu_f(c[nt][1] + bn.y));
        red_add_v2(g_agg + dst1 * 64 + n0, silu_f(c[nt][2] + bn.x), silu_f(c[nt][3] + bn.y));
    }
}

// ---------------------------------------------------------------------------
// node kernel (bf16 MMA): 64 nodes/block, 128 threads, warp owns 16 rows, N=128 (16 nt).
__global__ void __launch_bounds__(128) node_kernel_bf(
    const uint* __restrict__ w1f, const float* __restrict__ b1,
    const uint* __restrict__ w2f, const float* __restrict__ b2,
    const int* __restrict__ mask, float C)
{
    __shared__ __align__(16) __nv_bfloat16 As[64 * 72];    // A chunk
    __shared__ __align__(16) __nv_bfloat16 Ms[64 * 136];   // m1 [64][128], stride 136
    __shared__ uint Bf[4096];     // [ks4][nt16][lane][reg]
    int tid = threadIdx.x;
    int lane = tid & 31, w = tid >> 5;
    int g = lane >> 2, tig = lane & 3;
    int nblk = blockIdx.x * 64;
    int row0 = w * 16 + g;

    uint a_addr = smem_u32(As) + (uint)((w * 16 + (lane & 15)) * 144 + (lane >> 4) * 16);
    uint m_addr = smem_u32(Ms) + (uint)((w * 16 + (lane & 15)) * 272 + (lane >> 4) * 16);

    float c[16][4] = {};
    #pragma unroll
    for (int ch = 0; ch < 3; ch++) {
        if (ch) __syncthreads();
        {   // gather: 2 threads/node
            int e = tid >> 1, half = tid & 1;
            int node = nblk + e;
            if (ch < 2) {
                uint4* dp = (uint4*)(As + e * 72 + half * 32);
                if (node < N_NODES) {
                    const uint4* hp = (const uint4*)(g_hb + node * 128 + ch * 64) + half * 4;
                    dp[0] = hp[0]; dp[1] = hp[1]; dp[2] = hp[2]; dp[3] = hp[3];
                } else {
                    uint4 z = make_uint4(0, 0, 0, 0);
                    dp[0] = z; dp[1] = z; dp[2] = z; dp[3] = z;
                }
            } else {
                const float4* ap = (const float4*)(g_agg + node * 64) + half * 8;
                uint2* dp = (uint2*)(As + e * 72 + half * 32);
                #pragma unroll
                for (int j = 0; j < 8; j++) {
                    float4 v = (node < N_NODES) ? ap[j] : make_float4(0.f, 0.f, 0.f, 0.f);
                    uint2 pk;
                    pk.x = pack_bf16x2(v.x * C, v.y * C);
                    pk.y = pack_bf16x2(v.z * C, v.w * C);
                    dp[j] = pk;
                }
            }
        }
        {   // W1 chunk: 4096 uints = 16KB
            const uint4* wp = (const uint4*)(w1f + ch * 4096);
            uint4* bp = (uint4*)Bf;
            #pragma unroll
            for (int it = 0; it < 8; it++) bp[tid + it * 128] = wp[tid + it * 128];
        }
        __syncthreads();
        #pragma unroll
        for (int ks = 0; ks < 4; ks++) {
            uint a0, a1, a2, a3;
            ldsm_x4(a0, a1, a2, a3, a_addr + ks * 32);
            #pragma unroll
            for (int nt = 0; nt < 16; nt++) {
                uint2 b = *(const uint2*)(Bf + ((ks * 16 + nt) * 32 + lane) * 2);
                mma_bf16(c[nt], a0, a1, a2, a3, b.x, b.y);
            }
        }
    }
    __syncthreads();

    // m1 epilogue: bias+silu -> Ms (bf16)
    #pragma unroll
    for (int nt = 0; nt < 16; nt++) {
        int nn = nt * 8 + 2 * tig;
        float2 bn = *(const float2*)(b1 + nn);
        *(uint*)(Ms + row0 * 136 + nn) =
            pack_bf16x2(silu_f(c[nt][0] + bn.x), silu_f(c[nt][1] + bn.y));
        *(uint*)(Ms + (row0 + 8) * 136 + nn) =
            pack_bf16x2(silu_f(c[nt][2] + bn.x), silu_f(c[nt][3] + bn.y));
    }
    #pragma unroll
    for (int nt = 0; nt < 16; nt++) { c[nt][0] = c[nt][1] = c[nt][2] = c[nt][3] = 0.f; }

    // GEMM2: K=128, W2 fragments in two 16KB halves
    #pragma unroll
    for (int hf = 0; hf < 2; hf++) {
        __syncthreads();
        {
            const uint4* wp = (const uint4*)(w2f + hf * 4096);
            uint4* bp = (uint4*)Bf;
            #pragma unroll
            for (int it = 0; it < 8; it++) bp[tid + it * 128] = wp[tid + it * 128];
        }
        __syncthreads();
        #pragma unroll
        for (int ks = 0; ks < 4; ks++) {
            uint a0, a1, a2, a3;
            ldsm_x4(a0, a1, a2, a3, m_addr + (hf * 4 + ks) * 32);
            #pragma unroll
            for (int nt = 0; nt < 16; nt++) {
                uint2 b = *(const uint2*)(Bf + ((ks * 16 + nt) * 32 + lane) * 2);
                mma_bf16(c[nt], a0, a1, a2, a3, b.x, b.y);
            }
        }
    }

    // final: residual + mask (fp32), update g_h and mirror
    int node0 = nblk + row0, node1 = node0 + 8;
    int m0 = (node0 < N_NODES) ? mask[node0] : 0;
    int m1v = (node1 < N_NODES) ? mask[node1] : 0;
    #pragma unroll
    for (int nt = 0; nt < 16; nt++) {
        int nn = nt * 8 + 2 * tig;
        float2 bn = *(const float2*)(b2 + nn);
        if (m0) {
            float2 h = *(float2*)(g_h + node0 * 128 + nn);
            h.x += c[nt][0] + bn.x; h.y += c[nt][1] + bn.y;
            *(float2*)(g_h + node0 * 128 + nn) = h;
            *(uint*)(g_hb + node0 * 128 + nn) = pack_bf16x2(h.x, h.y);
        }
        if (m1v) {
            float2 h = *(float2*)(g_h + node1 * 128 + nn);
            h.x += c[nt][2] + bn.x; h.y += c[nt][3] + bn.y;
            *(float2*)(g_h + node1 * 128 + nn) = h;
            *(uint*)(g_hb + node1 * 128 + nn) = pack_bf16x2(h.x, h.y);
        }
    }
}

// ---------------------------------------------------------------------------
// emb_out: out[N,64] = g_h[N,128] @ W[128,64] + b  (fp32 scalar)
__global__ void __launch_bounds__(256) emb_out_kernel(
    const float* __restrict__ W, const float* __restrict__ b, float* __restrict__ out)
{
    __shared__ float As[64 * 68];
    __shared__ float Bs[64 * 64];
    int tid = threadIdx.x;
    int tx = tid & 15, ty = tid >> 4;
    int n0 = blockIdx.x * 64;

    float acc[4][4] = {};
    #pragma unroll
    for (int ch = 0; ch < 2; ch++) {
        if (ch) __syncthreads();
        {
            int n = tid >> 2, kk = tid & 3;
            int node = n0 + n;
            #pragma unroll
            for (int it = 0; it < 4; it++) {
                int k4 = kk + it * 4;
                float4 v = make_float4(0.f, 0.f, 0.f, 0.f);
                if (node < N_NODES) v = ((const float4*)(g_h + node * 128 + ch * 64))[k4];
                As[(k4*4+0)*68 + n] = v.x; As[(k4*4+1)*68 + n] = v.y;
                As[(k4*4+2)*68 + n] = v.z; As[(k4*4+3)*68 + n] = v.w;
            }
        }
        {
            const float4* wp = (const float4*)(W + ch * 64 * 64);
            float4* bp = (float4*)Bs;
            #pragma unroll
            for (int it = 0; it < 4; it++) bp[tid + it * 256] = wp[tid + it * 256];
        }
        __syncthreads();
        #pragma unroll
        for (int k = 0; k < 64; k++) {
            float4 a  = *(const float4*)(As + k * 68 + ty * 4);
            float4 bb = *(const float4*)(Bs + k * 64 + tx * 4);
            FMA16(a, bb, acc);
        }
    }
    float4 bias = *(const float4*)(b + tx * 4);
    #pragma unroll
    for (int i = 0; i < 4; i++) {
        int node = n0 + ty * 4 + i;
        if (node < N_NODES) {
            float4 v = make_float4(acc[i][0]+bias.x, acc[i][1]+bias.y,
                                   acc[i][2]+bias.z, acc[i][3]+bias.w);
            *((float4*)(out + node * 64) + tx) = v;
        }
    }
}

// ---------------------------------------------------------------------------
extern "C" void kernel_launch(void* const* d_in, const int* in_sizes, int n_in,
                              void* d_out, int out_size)
{
    (void)in_sizes; (void)n_in; (void)out_size;
    const float* h0     = (const float*)d_in[0];
    const int*   ea     = (const int*)d_in[1];      // [2, E]
    const int*   ebp    = (const int*)d_in[2];      // [2, E]
    const int*   ma     = (const int*)d_in[3];      // bool -> int32
    const int*   mb     = (const int*)d_in[4];      // bool -> int32
    const float* w_in   = (const float*)d_in[5];
    const float* b_in   = (const float*)d_in[6];
    const float* w_out  = (const float*)d_in[7];
    const float* b_out  = (const float*)d_in[8];
    const float* ew1    = (const float*)d_in[9];    // [4,256,64]
    const float* eb1    = (const float*)d_in[10];   // [4,64]
    const float* ew2    = (const float*)d_in[11];   // [4,64,64]
    const float* eb2    = (const float*)d_in[12];   // [4,64]
    const float* nw1    = (const float*)d_in[13];   // [4,192,128]
    const float* nb1    = (const float*)d_in[14];   // [4,128]
    const float* nw2    = (const float*)d_in[15];   // [4,128,128]
    const float* nb2    = (const float*)d_in[16];   // [4,128]
    float*       out    = (float*)d_out;

    uint* w1f_base;  cudaGetSymbolAddress((void**)&w1f_base,  g_w1f);
    uint* w2f_base;  cudaGetSymbolAddress((void**)&w2f_base,  g_w2f);
    uint* nw1f_base; cudaGetSymbolAddress((void**)&nw1f_base, g_nw1f);
    uint* nw2f_base; cudaGetSymbolAddress((void**)&nw2f_base, g_nw2f);

    prep_wfrag_bf<<<480, 256>>>(ew1, ew2, nw1, nw2);    // 122880 elements
    emb_in_kernel<<<(N_NODES + 31) / 32, 256>>>(h0, w_in, b_in);

    for (int l = 0; l < N_LAYERS; l++) {
        const int* er = (l & 1) ? ebp : ea;
        const int* m  = (l & 1) ? mb : ma;
        float C = (l & 1) ? (2.0f / 64.0f) : 1.0f;

        zero_agg_kernel<<<(N_NODES * EH / 4) / 256, 256>>>();
        edge_kernel_bf<<<E_TOTAL / 64, 128>>>(
            er, er + E_TOTAL,
            w1f_base + l * 8192, eb1 + l * 64,
            w2f_base + l * 2048, eb2 + l * 64);
        node_kernel_bf<<<(N_NODES + 63) / 64, 128>>>(
            nw1f_base + l * 12288, nb1 + l * 128,
            nw2f_base + l * 8192,  nb2 + l * 128, m, C);
    }

    emb_out_kernel<<<(N_NODES + 63) / 64, 256>>>(w_out, b_out, out);
}

// round 14
// speedup vs baseline: 4.9739x; 1.0331x over previous
#include <cuda_runtime.h>
#include <cuda_bf16.h>

#define N_NODES  50000
#define HID      128
#define EH       64
#define E_TOTAL  800000
#define N_LAYERS 4

typedef unsigned int uint;

// Persistent scratch (allowed: __device__ globals, no runtime alloc)
__device__ __align__(256) float g_h[N_NODES * HID];            // fp32 node features
__device__ __align__(256) __nv_bfloat16 g_hb[N_NODES * HID];   // bf16 mirror
__device__ __align__(256) float g_agg[N_NODES * EH];           // message accumulators
// bf16 fragment-ordered weights (built by prep kernel each launch)
__device__ __align__(256) uint g_w1f[4 * 4 * 4 * 8 * 32 * 2];    // edge W1: 32768
__device__ __align__(256) uint g_w2f[4 * 4 * 8 * 32 * 2];        // edge W2: 8192
__device__ __align__(256) uint g_nw1f[4 * 3 * 4 * 16 * 32 * 2];  // node W1: 49152
__device__ __align__(256) uint g_nw2f[4 * 8 * 16 * 32 * 2];      // node W2: 32768

__device__ __forceinline__ float silu_f(float x) {
    return x * (1.0f / (1.0f + __expf(-x)));
}
__device__ __forceinline__ void red_add_v2(float* p, float x, float y) {
    asm volatile("red.global.add.v2.f32 [%0], {%1,%2};" :: "l"(p), "f"(x), "f"(y) : "memory");
}
__device__ __forceinline__ uint smem_u32(const void* p) {
    return (uint)__cvta_generic_to_shared(p);
}
__device__ __forceinline__ void ldsm_x4(uint& r0, uint& r1, uint& r2, uint& r3, uint addr) {
    asm volatile("ldmatrix.sync.aligned.m8n8.x4.shared.b16 {%0,%1,%2,%3}, [%4];"
                 : "=r"(r0), "=r"(r1), "=r"(r2), "=r"(r3) : "r"(addr));
}
__device__ __forceinline__ void mma_bf16(float c[4], uint a0, uint a1, uint a2, uint a3,
                                         uint b0, uint b1) {
    asm("mma.sync.aligned.m16n8k16.row.col.f32.bf16.bf16.f32 "
        "{%0,%1,%2,%3},{%4,%5,%6,%7},{%8,%9},{%0,%1,%2,%3};"
        : "+f"(c[0]), "+f"(c[1]), "+f"(c[2]), "+f"(c[3])
        : "r"(a0), "r"(a1), "r"(a2), "r"(a3), "r"(b0), "r"(b1));
}
__device__ __forceinline__ uint pack_bf16x2(float lo, float hi) {
    __nv_bfloat162 p = __floats2bfloat162_rn(lo, hi);
    return *(uint*)&p;
}

#define FMA16(A4, B4, ACC) do { \
    ACC[0][0] += A4.x*B4.x; ACC[0][1] += A4.x*B4.y; ACC[0][2] += A4.x*B4.z; ACC[0][3] += A4.x*B4.w; \
    ACC[1][0] += A4.y*B4.x; ACC[1][1] += A4.y*B4.y; ACC[1][2] += A4.y*B4.z; ACC[1][3] += A4.y*B4.w; \
    ACC[2][0] += A4.z*B4.x; ACC[2][1] += A4.z*B4.y; ACC[2][2] += A4.z*B4.z; ACC[2][3] += A4.z*B4.w; \
    ACC[3][0] += A4.w*B4.x; ACC[3][1] += A4.w*B4.y; ACC[3][2] += A4.w*B4.z; ACC[3][3] += A4.w*B4.w; \
} while(0)

// ---------------------------------------------------------------------------
__global__ void zero_agg_kernel() {
    int i = blockIdx.x * blockDim.x + threadIdx.x;
    ((float4*)g_agg)[i] = make_float4(0.f, 0.f, 0.f, 0.f);
}

// ---------------------------------------------------------------------------
// Build all bf16 fragment-ordered weights (mma.m16n8k16.row.col B layout:
// reg r of lane (g,tig) = W[kbase + r*8 + 2*tig .. +1][n = nt*8 + g]).
__global__ void __launch_bounds__(256) prep_wfrag_bf(
    const float* __restrict__ ew1, const float* __restrict__ ew2,
    const float* __restrict__ nw1, const float* __restrict__ nw2)
{
    int i = blockIdx.x * 256 + threadIdx.x;     // 122880 total
    if (i < 32768) {            // edge W1: [l][ch4][ks4][nt8][lane][reg]
        int reg = i & 1, lane = (i >> 1) & 31, nt = (i >> 6) & 7,
            ks = (i >> 9) & 3, ch = (i >> 11) & 3, l = i >> 13;
        int g = lane >> 2, tig = lane & 3;
        int k = ch * 64 + ks * 16 + reg * 8 + 2 * tig;
        int n = nt * 8 + g;
        const float* base = ew1 + (l * 256 + k) * 64 + n;
        g_w1f[i] = pack_bf16x2(base[0], base[64]);
    } else if (i < 40960) {     // edge W2: [l][ks4][nt8][lane][reg]
        int j = i - 32768;
        int reg = j & 1, lane = (j >> 1) & 31, nt = (j >> 6) & 7,
            ks = (j >> 9) & 3, l = j >> 11;
        int g = lane >> 2, tig = lane & 3;
        int k = ks * 16 + reg * 8 + 2 * tig;
        int n = nt * 8 + g;
        const float* base = ew2 + (l * 64 + k) * 64 + n;
        g_w2f[j] = pack_bf16x2(base[0], base[64]);
    } else if (i < 90112) {     // node W1: [l][ch3][ks4][nt16][lane][reg]
        int j = i - 40960;
        int l = j / 12288, r = j % 12288;
        int ch = r >> 12, r2 = r & 4095;
        int ks = r2 >> 10, nt = (r2 >> 6) & 15, lane = (r2 >> 1) & 31, reg = r2 & 1;
        int g = lane >> 2, tig = lane & 3;
        int k = ch * 64 + ks * 16 + reg * 8 + 2 * tig;
        int n = nt * 8 + g;
        const float* base = nw1 + (l * 192 + k) * 128 + n;
        g_nw1f[j] = pack_bf16x2(base[0], base[128]);
    } else {                    // node W2: [l][ks8][nt16][lane][reg]
        int j = i - 90112;
        int l = j >> 13, r = j & 8191;
        int ks = r >> 10, nt = (r >> 6) & 15, lane = (r >> 1) & 31, reg = r & 1;
        int g = lane >> 2, tig = lane & 3;
        int k = ks * 16 + reg * 8 + 2 * tig;
        int n = nt * 8 + g;
        const float* base = nw2 + (l * 128 + k) * 128 + n;
        g_nw2f[j] = pack_bf16x2(base[0], base[128]);
    }
}

// ---------------------------------------------------------------------------
// emb_in: g_h[N,128] = x[N,64] @ W[64,128] + b ; also writes bf16 mirror
__global__ void __launch_bounds__(256) emb_in_kernel(
    const float* __restrict__ x, const float* __restrict__ W, const float* __restrict__ b)
{
    __shared__ float As[64 * 36];
    __shared__ float Bs[64 * 128];
    int tid = threadIdx.x;
    int tx = tid & 31, ty = tid >> 5;
    int n0 = blockIdx.x * 32;

    {
        int n = tid >> 3, kk = tid & 7;
        int node = n0 + n;
        #pragma unroll
        for (int it = 0; it < 2; it++) {
            int k4 = kk + it * 8;
            float4 v = make_float4(0.f, 0.f, 0.f, 0.f);
            if (node < N_NODES) v = ((const float4*)(x + node * 64))[k4];
            As[(k4*4+0)*36 + n] = v.x; As[(k4*4+1)*36 + n] = v.y;
            As[(k4*4+2)*36 + n] = v.z; As[(k4*4+3)*36 + n] = v.w;
        }
    }
    {
        const float4* wp = (const float4*)W;
        float4* bp = (float4*)Bs;
        #pragma unroll
        for (int it = 0; it < 8; it++) bp[tid + it * 256] = wp[tid + it * 256];
    }
    __syncthreads();

    float acc[4][4] = {};
    #pragma unroll
    for (int k = 0; k < 64; k++) {
        float4 a  = *(const float4*)(As + k * 36 + ty * 4);
        float4 bb = *(const float4*)(Bs + k * 128 + tx * 4);
        FMA16(a, bb, acc);
    }
    float4 bias = *(const float4*)(b + tx * 4);
    #pragma unroll
    for (int i = 0; i < 4; i++) {
        int node = n0 + ty * 4 + i;
        if (node < N_NODES) {
            float4 v = make_float4(acc[i][0]+bias.x, acc[i][1]+bias.y,
                                   acc[i][2]+bias.z, acc[i][3]+bias.w);
            *((float4*)(g_h + node * 128) + tx) = v;
            uint2 pk;
            pk.x = pack_bf16x2(v.x, v.y);
            pk.y = pack_bf16x2(v.z, v.w);
            *(uint2*)(g_hb + node * 128 + tx * 4) = pk;
        }
    }
}

// ---------------------------------------------------------------------------
// edge kernel (bf16 MMA, 2x2 warp split): 64 edges/block, 128 threads.
// Warp (rw,cw) owns 32 rows x 32 cols: 2 mtiles x 4 ntiles, accum = 32 regs.
// Per chunk LDS: A 4KB + B 4KB per warp (B bytes read 2x instead of 4x).
__global__ void __launch_bounds__(128) edge_kernel_bf(
    const int* __restrict__ erow, const int* __restrict__ ecol,
    const uint* __restrict__ w1f, const float* __restrict__ b1,
    const uint* __restrict__ w2f, const float* __restrict__ b2)
{
    __shared__ int sSrc[2][64];
    __shared__ __align__(16) __nv_bfloat16 As[64 * 72];  // reused for m1
    __shared__ uint Bf[2048];     // [ks(4)][nt(8)][lane(32)][reg(2)]
    int tid = threadIdx.x;
    int lane = tid & 31, w = tid >> 5;
    int g = lane >> 2, tig = lane & 3;
    int rw = w >> 1, cw = w & 1;          // 2x2 warp grid
    int e0 = blockIdx.x * 64;

    if (tid < 64) sSrc[0][tid]      = erow[e0 + tid];
    else          sSrc[1][tid - 64] = ecol[e0 + tid - 64];
    __syncthreads();

    // ldmatrix base: rows rw*32 + (lane&15), col-half (lane>>4); mtile 1 at +16 rows
    uint a_addr = smem_u32(As) + (uint)((rw * 32 + (lane & 15)) * 144 + (lane >> 4) * 16);

    float c[2][4][4] = {};
    #pragma unroll
    for (int ch = 0; ch < 4; ch++) {   // K chunks: row[0:64],row[64:128],col[0:64],col[64:128]
        if (ch) __syncthreads();
        {   // gather A chunk: 2 threads/edge, 4 x STS.128 each (64B)
            int e = tid >> 1, half = tid & 1;
            int src = sSrc[ch >> 1][e];
            const uint4* hp = (const uint4*)(g_hb + src * 128 + (ch & 1) * 64) + half * 4;
            uint4* dp = (uint4*)(As + e * 72 + half * 32);
            dp[0] = hp[0]; dp[1] = hp[1]; dp[2] = hp[2]; dp[3] = hp[3];
        }
        {   // W1 fragment chunk: 2048 uints = 8KB
            const uint4* wp = (const uint4*)(w1f + ch * 2048);
            uint4* bp = (uint4*)Bf;
            #pragma unroll
            for (int it = 0; it < 4; it++) bp[tid + it * 128] = wp[tid + it * 128];
        }
        __syncthreads();
        #pragma unroll
        for (int ks = 0; ks < 4; ks++) {
            uint a[2][4];
            ldsm_x4(a[0][0], a[0][1], a[0][2], a[0][3], a_addr + ks * 32);
            ldsm_x4(a[1][0], a[1][1], a[1][2], a[1][3], a_addr + 2304 + ks * 32);
            #pragma unroll
            for (int nt = 0; nt < 4; nt++) {
                int ntg = cw * 4 + nt;
                uint2 b = *(const uint2*)(Bf + ((ks * 8 + ntg) * 32 + lane) * 2);
                mma_bf16(c[0][nt], a[0][0], a[0][1], a[0][2], a[0][3], b.x, b.y);
                mma_bf16(c[1][nt], a[1][0], a[1][1], a[1][2], a[1][3], b.x, b.y);
            }
        }
    }
    __syncthreads();   // all GEMM1 smem reads done

    // m1 epilogue: bias+silu -> As (bf16, row-major, stride 72)
    #pragma unroll
    for (int mt = 0; mt < 2; mt++) {
        int r = rw * 32 + mt * 16 + g;
        #pragma unroll
        for (int nt = 0; nt < 4; nt++) {
            int n0 = cw * 32 + nt * 8 + 2 * tig;
            float2 bn = *(const float2*)(b1 + n0);
            *(uint*)(As + r * 72 + n0) =
                pack_bf16x2(silu_f(c[mt][nt][0] + bn.x), silu_f(c[mt][nt][1] + bn.y));
            *(uint*)(As + (r + 8) * 72 + n0) =
                pack_bf16x2(silu_f(c[mt][nt][2] + bn.x), silu_f(c[mt][nt][3] + bn.y));
        }
    }
    {   // W2 fragments: 2048 uints
        const uint4* wp = (const uint4*)w2f;
        uint4* bp = (uint4*)Bf;
        #pragma unroll
        for (int it = 0; it < 4; it++) bp[tid + it * 128] = wp[tid + it * 128];
    }
    #pragma unroll
    for (int mt = 0; mt < 2; mt++)
        #pragma unroll
        for (int nt = 0; nt < 4; nt++)
            c[mt][nt][0] = c[mt][nt][1] = c[mt][nt][2] = c[mt][nt][3] = 0.f;
    __syncthreads();

    // GEMM2: m2 = m1 @ W2, K=64
    #pragma unroll
    for (int ks = 0; ks < 4; ks++) {
        uint a[2][4];
        ldsm_x4(a[0][0], a[0][1], a[0][2], a[0][3], a_addr + ks * 32);
        ldsm_x4(a[1][0], a[1][1], a[1][2], a[1][3], a_addr + 2304 + ks * 32);
        #pragma unroll
        for (int nt = 0; nt < 4; nt++) {
            int ntg = cw * 4 + nt;
            uint2 b = *(const uint2*)(Bf + ((ks * 8 + ntg) * 32 + lane) * 2);
            mma_bf16(c[0][nt], a[0][0], a[0][1], a[0][2], a[0][3], b.x, b.y);
            mma_bf16(c[1][nt], a[1][0], a[1][1], a[1][2], a[1][3], b.x, b.y);
        }
    }

    // final epilogue: bias+silu, scatter-add (col half cw, rows rw*32..)
    #pragma unroll
    for (int mt = 0; mt < 2; mt++) {
        int r = rw * 32 + mt * 16 + g;
        int dst0 = sSrc[0][r], dst1 = sSrc[0][r + 8];
        #pragma unroll
        for (int nt = 0; nt < 4; nt++) {
            int n0 = cw * 32 + nt * 8 + 2 * tig;
            float2 bn = *(const float2*)(b2 + n0);
            red_add_v2(g_agg + dst0 * 64 + n0,
                       silu_f(c[mt][nt][0] + bn.x), silu_f(c[mt][nt][1] + bn.y));
            red_add_v2(g_agg + dst1 * 64 + n0,
                       silu_f(c[mt][nt][2] + bn.x), silu_f(c[mt][nt][3] + bn.y));
        }
    }
}

// ---------------------------------------------------------------------------
// node kernel (bf16 MMA): 64 nodes/block, 128 threads, warp owns 16 rows, N=128 (16 nt).
__global__ void __launch_bounds__(128) node_kernel_bf(
    const uint* __restrict__ w1f, const float* __restrict__ b1,
    const uint* __restrict__ w2f, const float* __restrict__ b2,
    const int* __restrict__ mask, float C)
{
    __shared__ __align__(16) __nv_bfloat16 As[64 * 72];    // A chunk
    __shared__ __align__(16) __nv_bfloat16 Ms[64 * 136];   // m1 [64][128], stride 136
    __shared__ uint Bf[4096];     // [ks4][nt16][lane][reg]
    int tid = threadIdx.x;
    int lane = tid & 31, w = tid >> 5;
    int g = lane >> 2, tig = lane & 3;
    int nblk = blockIdx.x * 64;
    int row0 = w * 16 + g;

    uint a_addr = smem_u32(As) + (uint)((w * 16 + (lane & 15)) * 144 + (lane >> 4) * 16);
    uint m_addr = smem_u32(Ms) + (uint)((w * 16 + (lane & 15)) * 272 + (lane >> 4) * 16);

    float c[16][4] = {};
    #pragma unroll
    for (int ch = 0; ch < 3; ch++) {
        if (ch) __syncthreads();
        {   // gather: 2 threads/node
            int e = tid >> 1, half = tid & 1;
            int node = nblk + e;
            if (ch < 2) {
                uint4* dp = (uint4*)(As + e * 72 + half * 32);
                if (node < N_NODES) {
                    const uint4* hp = (const uint4*)(g_hb + node * 128 + ch * 64) + half * 4;
                    dp[0] = hp[0]; dp[1] = hp[1]; dp[2] = hp[2]; dp[3] = hp[3];
                } else {
                    uint4 z = make_uint4(0, 0, 0, 0);
                    dp[0] = z; dp[1] = z; dp[2] = z; dp[3] = z;
                }
            } else {
                const float4* ap = (const float4*)(g_agg + node * 64) + half * 8;
                uint2* dp = (uint2*)(As + e * 72 + half * 32);
                #pragma unroll
                for (int j = 0; j < 8; j++) {
                    float4 v = (node < N_NODES) ? ap[j] : make_float4(0.f, 0.f, 0.f, 0.f);
                    uint2 pk;
                    pk.x = pack_bf16x2(v.x * C, v.y * C);
                    pk.y = pack_bf16x2(v.z * C, v.w * C);
                    dp[j] = pk;
                }
            }
        }
        {   // W1 chunk: 4096 uints = 16KB
            const uint4* wp = (const uint4*)(w1f + ch * 4096);
            uint4* bp = (uint4*)Bf;
            #pragma unroll
            for (int it = 0; it < 8; it++) bp[tid + it * 128] = wp[tid + it * 128];
        }
        __syncthreads();
        #pragma unroll
        for (int ks = 0; ks < 4; ks++) {
            uint a0, a1, a2, a3;
            ldsm_x4(a0, a1, a2, a3, a_addr + ks * 32);
            #pragma unroll
            for (int nt = 0; nt < 16; nt++) {
                uint2 b = *(const uint2*)(Bf + ((ks * 16 + nt) * 32 + lane) * 2);
                mma_bf16(c[nt], a0, a1, a2, a3, b.x, b.y);
            }
        }
    }
    __syncthreads();

    // m1 epilogue: bias+silu -> Ms (bf16)
    #pragma unroll
    for (int nt = 0; nt < 16; nt++) {
        int nn = nt * 8 + 2 * tig;
        float2 bn = *(const float2*)(b1 + nn);
        *(uint*)(Ms + row0 * 136 + nn) =
            pack_bf16x2(silu_f(c[nt][0] + bn.x), silu_f(c[nt][1] + bn.y));
        *(uint*)(Ms + (row0 + 8) * 136 + nn) =
            pack_bf16x2(silu_f(c[nt][2] + bn.x), silu_f(c[nt][3] + bn.y));
    }
    #pragma unroll
    for (int nt = 0; nt < 16; nt++) { c[nt][0] = c[nt][1] = c[nt][2] = c[nt][3] = 0.f; }

    // GEMM2: K=128, W2 fragments in two 16KB halves
    #pragma unroll
    for (int hf = 0; hf < 2; hf++) {
        __syncthreads();
        {
            const uint4* wp = (const uint4*)(w2f + hf * 4096);
            uint4* bp = (uint4*)Bf;
            #pragma unroll
            for (int it = 0; it < 8; it++) bp[tid + it * 128] = wp[tid + it * 128];
        }
        __syncthreads();
        #pragma unroll
        for (int ks = 0; ks < 4; ks++) {
            uint a0, a1, a2, a3;
            ldsm_x4(a0, a1, a2, a3, m_addr + (hf * 4 + ks) * 32);
            #pragma unroll
            for (int nt = 0; nt < 16; nt++) {
                uint2 b = *(const uint2*)(Bf + ((ks * 16 + nt) * 32 + lane) * 2);
                mma_bf16(c[nt], a0, a1, a2, a3, b.x, b.y);
            }
        }
    }

    // final: residual + mask (fp32), update g_h and mirror
    int node0 = nblk + row0, node1 = node0 + 8;
    int m0 = (node0 < N_NODES) ? mask[node0] : 0;
    int m1v = (node1 < N_NODES) ? mask[node1] : 0;
    #pragma unroll
    for (int nt = 0; nt < 16; nt++) {
        int nn = nt * 8 + 2 * tig;
        float2 bn = *(const float2*)(b2 + nn);
        if (m0) {
            float2 h = *(float2*)(g_h + node0 * 128 + nn);
            h.x += c[nt][0] + bn.x; h.y += c[nt][1] + bn.y;
            *(float2*)(g_h + node0 * 128 + nn) = h;
            *(uint*)(g_hb + node0 * 128 + nn) = pack_bf16x2(h.x, h.y);
        }
        if (m1v) {
            float2 h = *(float2*)(g_h + node1 * 128 + nn);
            h.x += c[nt][2] + bn.x; h.y += c[nt][3] + bn.y;
            *(float2*)(g_h + node1 * 128 + nn) = h;
            *(uint*)(g_hb + node1 * 128 + nn) = pack_bf16x2(h.x, h.y);
        }
    }
}

// ---------------------------------------------------------------------------
// emb_out: out[N,64] = g_h[N,128] @ W[128,64] + b  (fp32 scalar)
__global__ void __launch_bounds__(256) emb_out_kernel(
    const float* __restrict__ W, const float* __restrict__ b, float* __restrict__ out)
{
    __shared__ float As[64 * 68];
    __shared__ float Bs[64 * 64];
    int tid = threadIdx.x;
    int tx = tid & 15, ty = tid >> 4;
    int n0 = blockIdx.x * 64;

    float acc[4][4] = {};
    #pragma unroll
    for (int ch = 0; ch < 2; ch++) {
        if (ch) __syncthreads();
        {
            int n = tid >> 2, kk = tid & 3;
            int node = n0 + n;
            #pragma unroll
            for (int it = 0; it < 4; it++) {
                int k4 = kk + it * 4;
                float4 v = make_float4(0.f, 0.f, 0.f, 0.f);
                if (node < N_NODES) v = ((const float4*)(g_h + node * 128 + ch * 64))[k4];
                As[(k4*4+0)*68 + n] = v.x; As[(k4*4+1)*68 + n] = v.y;
                As[(k4*4+2)*68 + n] = v.z; As[(k4*4+3)*68 + n] = v.w;
            }
        }
        {
            const float4* wp = (const float4*)(W + ch * 64 * 64);
            float4* bp = (float4*)Bs;
            #pragma unroll
            for (int it = 0; it < 4; it++) bp[tid + it * 256] = wp[tid + it * 256];
        }
        __syncthreads();
        #pragma unroll
        for (int k = 0; k < 64; k++) {
            float4 a  = *(const float4*)(As + k * 68 + ty * 4);
            float4 bb = *(const float4*)(Bs + k * 64 + tx * 4);
            FMA16(a, bb, acc);
        }
    }
    float4 bias = *(const float4*)(b + tx * 4);
    #pragma unroll
    for (int i = 0; i < 4; i++) {
        int node = n0 + ty * 4 + i;
        if (node < N_NODES) {
            float4 v = make_float4(acc[i][0]+bias.x, acc[i][1]+bias.y,
                                   acc[i][2]+bias.z, acc[i][3]+bias.w);
            *((float4*)(out + node * 64) + tx) = v;
        }
    }
}

// ---------------------------------------------------------------------------
extern "C" void kernel_launch(void* const* d_in, const int* in_sizes, int n_in,
                              void* d_out, int out_size)
{
    (void)in_sizes; (void)n_in; (void)out_size;
    const float* h0     = (const float*)d_in[0];
    const int*   ea     = (const int*)d_in[1];      // [2, E]
    const int*   ebp    = (const int*)d_in[2];      // [2, E]
    const int*   ma     = (const int*)d_in[3];      // bool -> int32
    const int*   mb     = (const int*)d_in[4];      // bool -> int32
    const float* w_in   = (const float*)d_in[5];
    const float* b_in   = (const float*)d_in[6];
    const float* w_out  = (const float*)d_in[7];
    const float* b_out  = (const float*)d_in[8];
    const float* ew1    = (const float*)d_in[9];    // [4,256,64]
    const float* eb1    = (const float*)d_in[10];   // [4,64]
    const float* ew2    = (const float*)d_in[11];   // [4,64,64]
    const float* eb2    = (const float*)d_in[12];   // [4,64]
    const float* nw1    = (const float*)d_in[13];   // [4,192,128]
    const float* nb1    = (const float*)d_in[14];   // [4,128]
    const float* nw2    = (const float*)d_in[15];   // [4,128,128]
    const float* nb2    = (const float*)d_in[16];   // [4,128]
    float*       out    = (float*)d_out;

    uint* w1f_base;  cudaGetSymbolAddress((void**)&w1f_base,  g_w1f);
    uint* w2f_base;  cudaGetSymbolAddress((void**)&w2f_base,  g_w2f);
    uint* nw1f_base; cudaGetSymbolAddress((void**)&nw1f_base, g_nw1f);
    uint* nw2f_base; cudaGetSymbolAddress((void**)&nw2f_base, g_nw2f);

    prep_wfrag_bf<<<480, 256>>>(ew1, ew2, nw1, nw2);    // 122880 elements
    emb_in_kernel<<<(N_NODES + 31) / 32, 256>>>(h0, w_in, b_in);

    for (int l = 0; l < N_LAYERS; l++) {
        const int* er = (l & 1) ? ebp : ea;
        const int* m  = (l & 1) ? mb : ma;
        float C = (l & 1) ? (2.0f / 64.0f) : 1.0f;

        zero_agg_kernel<<<(N_NODES * EH / 4) / 256, 256>>>();
        edge_kernel_bf<<<E_TOTAL / 64, 128>>>(
            er, er + E_TOTAL,
            w1f_base + l * 8192, eb1 + l * 64,
            w2f_base + l * 2048, eb2 + l * 64);
        node_kernel_bf<<<(N_NODES + 63) / 64, 128>>>(
            nw1f_base + l * 12288, nb1 + l * 128,
            nw2f_base + l * 8192,  nb2 + l * 128, m, C);
    }

    emb_out_kernel<<<(N_NODES + 63) / 64, 256>>>(w_out, b_out, out);
}

// round 17
// speedup vs baseline: 5.2375x; 1.0530x over previous
#include <cuda_runtime.h>
#include <cuda_bf16.h>

#define N_NODES  50000
#define HID      128
#define EH       64
#define E_TOTAL  800000
#define N_LAYERS 4

typedef unsigned int uint;

// Persistent scratch (allowed: __device__ globals, no runtime alloc)
__device__ __align__(256) float g_h[N_NODES * HID];            // fp32 node features
__device__ __align__(256) __nv_bfloat16 g_hb[N_NODES * HID];   // bf16 mirror
__device__ __align__(256) float g_agg[N_NODES * EH];           // message accumulators
// bf16 fragment-ordered weights (built by prep kernel each launch)
__device__ __align__(256) uint g_w1f[4 * 4 * 4 * 8 * 32 * 2];    // edge W1: 32768
__device__ __align__(256) uint g_w2f[4 * 4 * 8 * 32 * 2];        // edge W2: 8192
__device__ __align__(256) uint g_nw1f[4 * 3 * 4 * 16 * 32 * 2];  // node W1: 49152
__device__ __align__(256) uint g_nw2f[4 * 8 * 16 * 32 * 2];      // node W2: 32768

__device__ __forceinline__ float silu_f(float x) {
    return x * (1.0f / (1.0f + __expf(-x)));
}
__device__ __forceinline__ void red_add_v2(float* p, float x, float y) {
    asm volatile("red.global.add.v2.f32 [%0], {%1,%2};" :: "l"(p), "f"(x), "f"(y) : "memory");
}
__device__ __forceinline__ uint smem_u32(const void* p) {
    return (uint)__cvta_generic_to_shared(p);
}
__device__ __forceinline__ void cp16(void* d, const void* s) {
    asm volatile("cp.async.cg.shared.global [%0], [%1], 16;"
                 :: "r"(smem_u32(d)), "l"(s) : "memory");
}
#define CP_COMMIT() asm volatile("cp.async.commit_group;" ::: "memory")
#define CP_WAIT0()  asm volatile("cp.async.wait_group 0;" ::: "memory")
__device__ __forceinline__ void ldsm_x4(uint& r0, uint& r1, uint& r2, uint& r3, uint addr) {
    asm volatile("ldmatrix.sync.aligned.m8n8.x4.shared.b16 {%0,%1,%2,%3}, [%4];"
                 : "=r"(r0), "=r"(r1), "=r"(r2), "=r"(r3) : "r"(addr));
}
__device__ __forceinline__ void mma_bf16(float c[4], uint a0, uint a1, uint a2, uint a3,
                                         uint b0, uint b1) {
    asm("mma.sync.aligned.m16n8k16.row.col.f32.bf16.bf16.f32 "
        "{%0,%1,%2,%3},{%4,%5,%6,%7},{%8,%9},{%0,%1,%2,%3};"
        : "+f"(c[0]), "+f"(c[1]), "+f"(c[2]), "+f"(c[3])
        : "r"(a0), "r"(a1), "r"(a2), "r"(a3), "r"(b0), "r"(b1));
}
__device__ __forceinline__ uint pack_bf16x2(float lo, float hi) {
    __nv_bfloat162 p = __floats2bfloat162_rn(lo, hi);
    return *(uint*)&p;
}

#define FMA16(A4, B4, ACC) do { \
    ACC[0][0] += A4.x*B4.x; ACC[0][1] += A4.x*B4.y; ACC[0][2] += A4.x*B4.z; ACC[0][3] += A4.x*B4.w; \
    ACC[1][0] += A4.y*B4.x; ACC[1][1] += A4.y*B4.y; ACC[1][2] += A4.y*B4.z; ACC[1][3] += A4.y*B4.w; \
    ACC[2][0] += A4.z*B4.x; ACC[2][1] += A4.z*B4.y; ACC[2][2] += A4.z*B4.z; ACC[2][3] += A4.z*B4.w; \
    ACC[3][0] += A4.w*B4.x; ACC[3][1] += A4.w*B4.y; ACC[3][2] += A4.w*B4.z; ACC[3][3] += A4.w*B4.w; \
} while(0)

// ---------------------------------------------------------------------------
__global__ void zero_agg_kernel() {
    int i = blockIdx.x * blockDim.x + threadIdx.x;
    ((float4*)g_agg)[i] = make_float4(0.f, 0.f, 0.f, 0.f);
}

// ---------------------------------------------------------------------------
// Build all bf16 fragment-ordered weights (mma.m16n8k16.row.col B layout:
// reg r of lane (g,tig) = W[kbase + r*8 + 2*tig .. +1][n = nt*8 + g]).
__global__ void __launch_bounds__(256) prep_wfrag_bf(
    const float* __restrict__ ew1, const float* __restrict__ ew2,
    const float* __restrict__ nw1, const float* __restrict__ nw2)
{
    int i = blockIdx.x * 256 + threadIdx.x;     // 122880 total
    if (i < 32768) {            // edge W1: [l][ch4][ks4][nt8][lane][reg]
        int reg = i & 1, lane = (i >> 1) & 31, nt = (i >> 6) & 7,
            ks = (i >> 9) & 3, ch = (i >> 11) & 3, l = i >> 13;
        int g = lane >> 2, tig = lane & 3;
        int k = ch * 64 + ks * 16 + reg * 8 + 2 * tig;
        int n = nt * 8 + g;
        const float* base = ew1 + (l * 256 + k) * 64 + n;
        g_w1f[i] = pack_bf16x2(base[0], base[64]);
    } else if (i < 40960) {     // edge W2: [l][ks4][nt8][lane][reg]
        int j = i - 32768;
        int reg = j & 1, lane = (j >> 1) & 31, nt = (j >> 6) & 7,
            ks = (j >> 9) & 3, l = j >> 11;
        int g = lane >> 2, tig = lane & 3;
        int k = ks * 16 + reg * 8 + 2 * tig;
        int n = nt * 8 + g;
        const float* base = ew2 + (l * 64 + k) * 64 + n;
        g_w2f[j] = pack_bf16x2(base[0], base[64]);
    } else if (i < 90112) {     // node W1: [l][ch3][ks4][nt16][lane][reg]
        int j = i - 40960;
        int l = j / 12288, r = j % 12288;
        int ch = r >> 12, r2 = r & 4095;
        int ks = r2 >> 10, nt = (r2 >> 6) & 15, lane = (r2 >> 1) & 31, reg = r2 & 1;
        int g = lane >> 2, tig = lane & 3;
        int k = ch * 64 + ks * 16 + reg * 8 + 2 * tig;
        int n = nt * 8 + g;
        const float* base = nw1 + (l * 192 + k) * 128 + n;
        g_nw1f[j] = pack_bf16x2(base[0], base[128]);
    } else {                    // node W2: [l][ks8][nt16][lane][reg]
        int j = i - 90112;
        int l = j >> 13, r = j & 8191;
        int ks = r >> 10, nt = (r >> 6) & 15, lane = (r >> 1) & 31, reg = r & 1;
        int g = lane >> 2, tig = lane & 3;
        int k = ks * 16 + reg * 8 + 2 * tig;
        int n = nt * 8 + g;
        const float* base = nw2 + (l * 128 + k) * 128 + n;
        g_nw2f[j] = pack_bf16x2(base[0], base[128]);
    }
}

// ---------------------------------------------------------------------------
// emb_in: g_h[N,128] = x[N,64] @ W[64,128] + b ; also writes bf16 mirror
__global__ void __launch_bounds__(256) emb_in_kernel(
    const float* __restrict__ x, const float* __restrict__ W, const float* __restrict__ b)
{
    __shared__ float As[64 * 36];
    __shared__ float Bs[64 * 128];
    int tid = threadIdx.x;
    int tx = tid & 31, ty = tid >> 5;
    int n0 = blockIdx.x * 32;

    {
        int n = tid >> 3, kk = tid & 7;
        int node = n0 + n;
        #pragma unroll
        for (int it = 0; it < 2; it++) {
            int k4 = kk + it * 8;
            float4 v = make_float4(0.f, 0.f, 0.f, 0.f);
            if (node < N_NODES) v = ((const float4*)(x + node * 64))[k4];
            As[(k4*4+0)*36 + n] = v.x; As[(k4*4+1)*36 + n] = v.y;
            As[(k4*4+2)*36 + n] = v.z; As[(k4*4+3)*36 + n] = v.w;
        }
    }
    {
        const float4* wp = (const float4*)W;
        float4* bp = (float4*)Bs;
        #pragma unroll
        for (int it = 0; it < 8; it++) bp[tid + it * 256] = wp[tid + it * 256];
    }
    __syncthreads();

    float acc[4][4] = {};
    #pragma unroll
    for (int k = 0; k < 64; k++) {
        float4 a  = *(const float4*)(As + k * 36 + ty * 4);
        float4 bb = *(const float4*)(Bs + k * 128 + tx * 4);
        FMA16(a, bb, acc);
    }
    float4 bias = *(const float4*)(b + tx * 4);
    #pragma unroll
    for (int i = 0; i < 4; i++) {
        int node = n0 + ty * 4 + i;
        if (node < N_NODES) {
            float4 v = make_float4(acc[i][0]+bias.x, acc[i][1]+bias.y,
                                   acc[i][2]+bias.z, acc[i][3]+bias.w);
            *((float4*)(g_h + node * 128) + tx) = v;
            uint2 pk;
            pk.x = pack_bf16x2(v.x, v.y);
            pk.y = pack_bf16x2(v.z, v.w);
            *(uint2*)(g_hb + node * 128 + tx * 4) = pk;
        }
    }
}

// ---------------------------------------------------------------------------
// edge kernel (bf16 MMA, 2x2 warp split + cp.async double-buffered pipeline):
// 64 edges/block, 128 threads. Warp (rw,cw) owns 32 rows x 32 cols.
// GEMM1 K=256 (4 chunks), GEMM2 K=64. Chunk ch+1 staged via cp.async (LDGSTS)
// while chunk ch runs MMA; W2 prefetched during the last GEMM1 chunk.
__global__ void __launch_bounds__(128) edge_kernel_bf(
    const int* __restrict__ erow, const int* __restrict__ ecol,
    const uint* __restrict__ w1f, const float* __restrict__ b1,
    const uint* __restrict__ w2f, const float* __restrict__ b2)
{
    __shared__ int sSrc[2][64];
    __shared__ __align__(16) __nv_bfloat16 As[2 * 64 * 72];  // buf stride 9216B
    __shared__ __align__(16) uint Bf[2 * 2048];              // buf stride 8192B
    int tid = threadIdx.x;
    int lane = tid & 31, w = tid >> 5;
    int g = lane >> 2, tig = lane & 3;
    int rw = w >> 1, cw = w & 1;          // 2x2 warp grid
    int e0 = blockIdx.x * 64;

    if (tid < 64) sSrc[0][tid]      = erow[e0 + tid];
    else          sSrc[1][tid - 64] = ecol[e0 + tid - 64];
    __syncthreads();

    int e = tid >> 1, half = tid & 1;
    uint a0_addr = smem_u32(As) + (uint)((rw * 32 + (lane & 15)) * 144 + (lane >> 4) * 16);

    // Prologue: issue chunk 0 (A gather + W1 chunk 0) into buffer 0
    {
        int src = sSrc[0][e];
        const char* sp = (const char*)(g_hb + src * 128) + half * 64;
        char* dp = (char*)As + e * 144 + half * 64;
        #pragma unroll
        for (int j = 0; j < 4; j++) cp16(dp + j * 16, sp + j * 16);
        const char* wsp = (const char*)w1f;
        char* wdp = (char*)Bf;
        #pragma unroll
        for (int it = 0; it < 4; it++)
            cp16(wdp + (tid + it * 128) * 16, wsp + (tid + it * 128) * 16);
        CP_COMMIT();
    }

    float c[2][4][4] = {};
    #pragma unroll
    for (int ch = 0; ch < 4; ch++) {
        CP_WAIT0();          // chunk ch copies (this thread's) done
        __syncthreads();     // all copies visible; prior-chunk smem reads done
        if (ch < 3) {        // stage chunk ch+1 into buffer (ch+1)&1
            int nc = ch + 1;
            int src = sSrc[nc >> 1][e];
            const char* sp = (const char*)(g_hb + src * 128 + (nc & 1) * 64) + half * 64;
            char* dp = (char*)As + (nc & 1) * 9216 + e * 144 + half * 64;
            #pragma unroll
            for (int j = 0; j < 4; j++) cp16(dp + j * 16, sp + j * 16);
            const char* wsp = (const char*)(w1f + nc * 2048);
            char* wdp = (char*)Bf + (nc & 1) * 8192;
            #pragma unroll
            for (int it = 0; it < 4; it++)
                cp16(wdp + (tid + it * 128) * 16, wsp + (tid + it * 128) * 16);
        } else {             // prefetch W2 into Bf[0] (last Bf[0] reads were chunk 2)
            const char* wsp = (const char*)w2f;
            char* wdp = (char*)Bf;
            #pragma unroll
            for (int it = 0; it < 4; it++)
                cp16(wdp + (tid + it * 128) * 16, wsp + (tid + it * 128) * 16);
        }
        CP_COMMIT();
        // MMA on buffer ch&1 (2x2 split)
        uint abase = a0_addr + (uint)((ch & 1) * 9216);
        const uint* bfc = Bf + (ch & 1) * 2048;
        #pragma unroll
        for (int ks = 0; ks < 4; ks++) {
            uint a[2][4];
            ldsm_x4(a[0][0], a[0][1], a[0][2], a[0][3], abase + ks * 32);
            ldsm_x4(a[1][0], a[1][1], a[1][2], a[1][3], abase + 2304 + ks * 32);
            #pragma unroll
            for (int nt = 0; nt < 4; nt++) {
                int ntg = cw * 4 + nt;
                uint2 b = *(const uint2*)(bfc + ((ks * 8 + ntg) * 32 + lane) * 2);
                mma_bf16(c[0][nt], a[0][0], a[0][1], a[0][2], a[0][3], b.x, b.y);
                mma_bf16(c[1][nt], a[1][0], a[1][1], a[1][2], a[1][3], b.x, b.y);
            }
        }
    }

    // m1 epilogue: bias+silu -> As buffer 0 (chunk-2 reads done; chunk-3 used buf 1)
    #pragma unroll
    for (int mt = 0; mt < 2; mt++) {
        int r = rw * 32 + mt * 16 + g;
        #pragma unroll
        for (int nt = 0; nt < 4; nt++) {
            int n0 = cw * 32 + nt * 8 + 2 * tig;
            float2 bn = *(const float2*)(b1 + n0);
            *(uint*)(As + r * 72 + n0) =
                pack_bf16x2(silu_f(c[mt][nt][0] + bn.x), silu_f(c[mt][nt][1] + bn.y));
            *(uint*)(As + (r + 8) * 72 + n0) =
                pack_bf16x2(silu_f(c[mt][nt][2] + bn.x), silu_f(c[mt][nt][3] + bn.y));
        }
    }
    #pragma unroll
    for (int mt = 0; mt < 2; mt++)
        #pragma unroll
        for (int nt = 0; nt < 4; nt++)
            c[mt][nt][0] = c[mt][nt][1] = c[mt][nt][2] = c[mt][nt][3] = 0.f;
    CP_WAIT0();          // W2 fragments arrived in Bf[0]
    __syncthreads();     // m1 + W2 visible to all

    // GEMM2: m2 = m1 @ W2, K=64 (buffer 0)
    #pragma unroll
    for (int ks = 0; ks < 4; ks++) {
        uint a[2][4];
        ldsm_x4(a[0][0], a[0][1], a[0][2], a[0][3], a0_addr + ks * 32);
        ldsm_x4(a[1][0], a[1][1], a[1][2], a[1][3], a0_addr + 2304 + ks * 32);
        #pragma unroll
        for (int nt = 0; nt < 4; nt++) {
            int ntg = cw * 4 + nt;
            uint2 b = *(const uint2*)(Bf + ((ks * 8 + ntg) * 32 + lane) * 2);
            mma_bf16(c[0][nt], a[0][0], a[0][1], a[0][2], a[0][3], b.x, b.y);
            mma_bf16(c[1][nt], a[1][0], a[1][1], a[1][2], a[1][3], b.x, b.y);
        }
    }

    // final epilogue: bias+silu, scatter-add (col half cw, rows rw*32..)
    #pragma unroll
    for (int mt = 0; mt < 2; mt++) {
        int r = rw * 32 + mt * 16 + g;
        int dst0 = sSrc[0][r], dst1 = sSrc[0][r + 8];
        #pragma unroll
        for (int nt = 0; nt < 4; nt++) {
            int n0 = cw * 32 + nt * 8 + 2 * tig;
            float2 bn = *(const float2*)(b2 + n0);
            red_add_v2(g_agg + dst0 * 64 + n0,
                       silu_f(c[mt][nt][0] + bn.x), silu_f(c[mt][nt][1] + bn.y));
            red_add_v2(g_agg + dst1 * 64 + n0,
                       silu_f(c[mt][nt][2] + bn.x), silu_f(c[mt][nt][3] + bn.y));
        }
    }
}

// ---------------------------------------------------------------------------
// node kernel (bf16 MMA): 64 nodes/block, 128 threads, warp owns 16 rows, N=128 (16 nt).
__global__ void __launch_bounds__(128) node_kernel_bf(
    const uint* __restrict__ w1f, const float* __restrict__ b1,
    const uint* __restrict__ w2f, const float* __restrict__ b2,
    const int* __restrict__ mask, float C)
{
    __shared__ __align__(16) __nv_bfloat16 As[64 * 72];    // A chunk
    __shared__ __align__(16) __nv_bfloat16 Ms[64 * 136];   // m1 [64][128], stride 136
    __shared__ uint Bf[4096];     // [ks4][nt16][lane][reg]
    int tid = threadIdx.x;
    int lane = tid & 31, w = tid >> 5;
    int g = lane >> 2, tig = lane & 3;
    int nblk = blockIdx.x * 64;
    int row0 = w * 16 + g;

    uint a_addr = smem_u32(As) + (uint)((w * 16 + (lane & 15)) * 144 + (lane >> 4) * 16);
    uint m_addr = smem_u32(Ms) + (uint)((w * 16 + (lane & 15)) * 272 + (lane >> 4) * 16);

    float c[16][4] = {};
    #pragma unroll
    for (int ch = 0; ch < 3; ch++) {
        if (ch) __syncthreads();
        {   // gather: 2 threads/node
            int e = tid >> 1, half = tid & 1;
            int node = nblk + e;
            if (ch < 2) {
                uint4* dp = (uint4*)(As + e * 72 + half * 32);
                if (node < N_NODES) {
                    const uint4* hp = (const uint4*)(g_hb + node * 128 + ch * 64) + half * 4;
                    dp[0] = hp[0]; dp[1] = hp[1]; dp[2] = hp[2]; dp[3] = hp[3];
                } else {
                    uint4 z = make_uint4(0, 0, 0, 0);
                    dp[0] = z; dp[1] = z; dp[2] = z; dp[3] = z;
                }
            } else {
                const float4* ap = (const float4*)(g_agg + node * 64) + half * 8;
                uint2* dp = (uint2*)(As + e * 72 + half * 32);
                #pragma unroll
                for (int j = 0; j < 8; j++) {
                    float4 v = (node < N_NODES) ? ap[j] : make_float4(0.f, 0.f, 0.f, 0.f);
                    uint2 pk;
                    pk.x = pack_bf16x2(v.x * C, v.y * C);
                    pk.y = pack_bf16x2(v.z * C, v.w * C);
                    dp[j] = pk;
                }
            }
        }
        {   // W1 chunk: 4096 uints = 16KB
            const uint4* wp = (const uint4*)(w1f + ch * 4096);
            uint4* bp = (uint4*)Bf;
            #pragma unroll
            for (int it = 0; it < 8; it++) bp[tid + it * 128] = wp[tid + it * 128];
        }
        __syncthreads();
        #pragma unroll
        for (int ks = 0; ks < 4; ks++) {
            uint a0, a1, a2, a3;
            ldsm_x4(a0, a1, a2, a3, a_addr + ks * 32);
            #pragma unroll
            for (int nt = 0; nt < 16; nt++) {
                uint2 b = *(const uint2*)(Bf + ((ks * 16 + nt) * 32 + lane) * 2);
                mma_bf16(c[nt], a0, a1, a2, a3, b.x, b.y);
            }
        }
    }
    __syncthreads();

    // m1 epilogue: bias+silu -> Ms (bf16)
    #pragma unroll
    for (int nt = 0; nt < 16; nt++) {
        int nn = nt * 8 + 2 * tig;
        float2 bn = *(const float2*)(b1 + nn);
        *(uint*)(Ms + row0 * 136 + nn) =
            pack_bf16x2(silu_f(c[nt][0] + bn.x), silu_f(c[nt][1] + bn.y));
        *(uint*)(Ms + (row0 + 8) * 136 + nn) =
            pack_bf16x2(silu_f(c[nt][2] + bn.x), silu_f(c[nt][3] + bn.y));
    }
    #pragma unroll
    for (int nt = 0; nt < 16; nt++) { c[nt][0] = c[nt][1] = c[nt][2] = c[nt][3] = 0.f; }

    // GEMM2: K=128, W2 fragments in two 16KB halves
    #pragma unroll
    for (int hf = 0; hf < 2; hf++) {
        __syncthreads();
        {
            const uint4* wp = (const uint4*)(w2f + hf * 4096);
            uint4* bp = (uint4*)Bf;
            #pragma unroll
            for (int it = 0; it < 8; it++) bp[tid + it * 128] = wp[tid + it * 128];
        }
        __syncthreads();
        #pragma unroll
        for (int ks = 0; ks < 4; ks++) {
            uint a0, a1, a2, a3;
            ldsm_x4(a0, a1, a2, a3, m_addr + (hf * 4 + ks) * 32);
            #pragma unroll
            for (int nt = 0; nt < 16; nt++) {
                uint2 b = *(const uint2*)(Bf + ((ks * 16 + nt) * 32 + lane) * 2);
                mma_bf16(c[nt], a0, a1, a2, a3, b.x, b.y);
            }
        }
    }

    // final: residual + mask (fp32), update g_h and mirror
    int node0 = nblk + row0, node1 = node0 + 8;
    int m0 = (node0 < N_NODES) ? mask[node0] : 0;
    int m1v = (node1 < N_NODES) ? mask[node1] : 0;
    #pragma unroll
    for (int nt = 0; nt < 16; nt++) {
        int nn = nt * 8 + 2 * tig;
        float2 bn = *(const float2*)(b2 + nn);
        if (m0) {
            float2 h = *(float2*)(g_h + node0 * 128 + nn);
            h.x += c[nt][0] + bn.x; h.y += c[nt][1] + bn.y;
            *(float2*)(g_h + node0 * 128 + nn) = h;
            *(uint*)(g_hb + node0 * 128 + nn) = pack_bf16x2(h.x, h.y);
        }
        if (m1v) {
            float2 h = *(float2*)(g_h + node1 * 128 + nn);
            h.x += c[nt][2] + bn.x; h.y += c[nt][3] + bn.y;
            *(float2*)(g_h + node1 * 128 + nn) = h;
            *(uint*)(g_hb + node1 * 128 + nn) = pack_bf16x2(h.x, h.y);
        }
    }
}

// ---------------------------------------------------------------------------
// emb_out: out[N,64] = g_h[N,128] @ W[128,64] + b  (fp32 scalar)
__global__ void __launch_bounds__(256) emb_out_kernel(
    const float* __restrict__ W, const float* __restrict__ b, float* __restrict__ out)
{
    __shared__ float As[64 * 68];
    __shared__ float Bs[64 * 64];
    int tid = threadIdx.x;
    int tx = tid & 15, ty = tid >> 4;
    int n0 = blockIdx.x * 64;

    float acc[4][4] = {};
    #pragma unroll
    for (int ch = 0; ch < 2; ch++) {
        if (ch) __syncthreads();
        {
            int n = tid >> 2, kk = tid & 3;
            int node = n0 + n;
            #pragma unroll
            for (int it = 0; it < 4; it++) {
                int k4 = kk + it * 4;
                float4 v = make_float4(0.f, 0.f, 0.f, 0.f);
                if (node < N_NODES) v = ((const float4*)(g_h + node * 128 + ch * 64))[k4];
                As[(k4*4+0)*68 + n] = v.x; As[(k4*4+1)*68 + n] = v.y;
                As[(k4*4+2)*68 + n] = v.z; As[(k4*4+3)*68 + n] = v.w;
            }
        }
        {
            const float4* wp = (const float4*)(W + ch * 64 * 64);
            float4* bp = (float4*)Bs;
            #pragma unroll
            for (int it = 0; it < 4; it++) bp[tid + it * 256] = wp[tid + it * 256];
        }
        __syncthreads();
        #pragma unroll
        for (int k = 0; k < 64; k++) {
            float4 a  = *(const float4*)(As + k * 68 + ty * 4);
            float4 bb = *(const float4*)(Bs + k * 64 + tx * 4);
            FMA16(a, bb, acc);
        }
    }
    float4 bias = *(const float4*)(b + tx * 4);
    #pragma unroll
    for (int i = 0; i < 4; i++) {
        int node = n0 + ty * 4 + i;
        if (node < N_NODES) {
            float4 v = make_float4(acc[i][0]+bias.x, acc[i][1]+bias.y,
                                   acc[i][2]+bias.z, acc[i][3]+bias.w);
            *((float4*)(out + node * 64) + tx) = v;
        }
    }
}

// ---------------------------------------------------------------------------
extern "C" void kernel_launch(void* const* d_in, const int* in_sizes, int n_in,
                              void* d_out, int out_size)
{
    (void)in_sizes; (void)n_in; (void)out_size;
    const float* h0     = (const float*)d_in[0];
    const int*   ea     = (const int*)d_in[1];      // [2, E]
    const int*   ebp    = (const int*)d_in[2];      // [2, E]
    const int*   ma     = (const int*)d_in[3];      // bool -> int32
    const int*   mb     = (const int*)d_in[4];      // bool -> int32
    const float* w_in   = (const float*)d_in[5];
    const float* b_in   = (const float*)d_in[6];
    const float* w_out  = (const float*)d_in[7];
    const float* b_out  = (const float*)d_in[8];
    const float* ew1    = (const float*)d_in[9];    // [4,256,64]
    const float* eb1    = (const float*)d_in[10];   // [4,64]
    const float* ew2    = (const float*)d_in[11];   // [4,64,64]
    const float* eb2    = (const float*)d_in[12];   // [4,64]
    const float* nw1    = (const float*)d_in[13];   // [4,192,128]
    const float* nb1    = (const float*)d_in[14];   // [4,128]
    const float* nw2    = (const float*)d_in[15];   // [4,128,128]
    const float* nb2    = (const float*)d_in[16];   // [4,128]
    float*       out    = (float*)d_out;

    uint* w1f_base;  cudaGetSymbolAddress((void**)&w1f_base,  g_w1f);
    uint* w2f_base;  cudaGetSymbolAddress((void**)&w2f_base,  g_w2f);
    uint* nw1f_base; cudaGetSymbolAddress((void**)&nw1f_base, g_nw1f);
    uint* nw2f_base; cudaGetSymbolAddress((void**)&nw2f_base, g_nw2f);

    prep_wfrag_bf<<<480, 256>>>(ew1, ew2, nw1, nw2);    // 122880 elements
    emb_in_kernel<<<(N_NODES + 31) / 32, 256>>>(h0, w_in, b_in);

    for (int l = 0; l < N_LAYERS; l++) {
        const int* er = (l & 1) ? ebp : ea;
        const int* m  = (l & 1) ? mb : ma;
        float C = (l & 1) ? (2.0f / 64.0f) : 1.0f;

        zero_agg_kernel<<<(N_NODES * EH / 4) / 256, 256>>>();
        edge_kernel_bf<<<E_TOTAL / 64, 128>>>(
            er, er + E_TOTAL,
            w1f_base + l * 8192, eb1 + l * 64,
            w2f_base + l * 2048, eb2 + l * 64);
        node_kernel_bf<<<(N_NODES + 63) / 64, 128>>>(
            nw1f_base + l * 12288, nb1 + l * 128,
            nw2f_base + l * 8192,  nb2 + l * 128, m, C);
    }

    emb_out_kernel<<<(N_NODES + 63) / 64, 256>>>(w_out, b_out, out);
}